// round 10
// baseline (speedup 1.0000x reference)
#include <cuda_runtime.h>
#include <cstdint>
#include <cstddef>

// ---------------------------------------------------------------------------
// Packed fp32x2 FMA (sm_103a): 2 independent fp32 MACs per instruction.
// ---------------------------------------------------------------------------
__device__ __forceinline__ void fma2(float2 &c, const float2 a, const float2 b) {
    asm("fma.rn.f32x2 %0, %1, %2, %0;"
        : "+l"(reinterpret_cast<unsigned long long &>(c))
        : "l"(reinterpret_cast<const unsigned long long &>(const_cast<float2 &>(a))),
          "l"(reinterpret_cast<const unsigned long long &>(const_cast<float2 &>(b))));
}

// cp.async helpers (16B)
__device__ __forceinline__ void cpa16(void* s, const void* g) {
    unsigned saddr = (unsigned)__cvta_generic_to_shared(s);
    asm volatile("cp.async.cg.shared.global [%0], [%1], 16;\n" :: "r"(saddr), "l"(g));
}
__device__ __forceinline__ void cpa_commit() { asm volatile("cp.async.commit_group;\n"); }
__device__ __forceinline__ void cpa_wait0()  { asm volatile("cp.async.wait_group 0;\n"); }

// ---------------------------------------------------------------------------
// Scratch (device globals; allocation-free contract)
// ---------------------------------------------------------------------------
__device__ __align__(16) float g_x1[2048u * 32u * 1521u];   // conv1 out
__device__ __align__(16) float g_x2[2048u * 64u * 324u];    // conv2 out
__device__ __align__(16) float g_feat[2048u * 4096u];       // conv3 out / flattened
__device__ __align__(16) float g_keys[2048u * 256u];
__device__ __align__(16) float g_vals[2048u * 256u];
__device__ __align__(16) float g_gif[2048u * 768u];         // feat-part of GRU gi (+b_ih)
__device__ __align__(16) float g_hseq[2048u * 256u];
__device__ __align__(16) float g_oseq[2048u * 256u];
__device__ __align__(16) float g_gbuf[2048u * 256u];        // relu(hseq@Wh^T + oseq)
__device__ __align__(16) float g_w2t[800u * 64u];           // conv2 weights transposed [r][oc]
__device__ __align__(16) float g_w3t[576u * 64u];           // conv3 weights transposed [r][oc]

// ---------------------------------------------------------------------------
// weight transposes (oc-contiguous)
// ---------------------------------------------------------------------------
__global__ void w2t_k(const float* __restrict__ w) {
    int i = blockIdx.x * 256 + threadIdx.x;   // 51200
    if (i < 51200) {
        int r = i >> 6, oc = i & 63;
        g_w2t[i] = w[oc * 800 + r];
    }
}
__global__ void w3t_k(const float* __restrict__ w) {
    int i = blockIdx.x * 256 + threadIdx.x;   // 36864
    if (i < 36864) {
        int r = i >> 6, oc = i & 63;
        g_w3t[i] = w[oc * 576 + r];
    }
}

// ---------------------------------------------------------------------------
// conv1: [2048,3,84,84] -> [2048,32,39,39], 7x7 s2, ReLU. 512 threads.
// Thread tile: 8 oc x 3 consecutive-x outputs; kx register-sliding window.
// Rows of 39 = 13 segments of 3; 507 segments over 4 iterations of 128.
// ---------------------------------------------------------------------------
__global__ __launch_bounds__(512, 1) void conv1_k(const float* __restrict__ obs,
                                                  const float* __restrict__ w,
                                                  const float* __restrict__ bia) {
    extern __shared__ float sm[];
    float* in_s = sm;            // 21168
    float* w_s  = sm + 21168;    // 4704
    const int n = blockIdx.x;
    const float* src = obs + (size_t)n * 21168;
    for (int i = threadIdx.x; i < 21168; i += 512) in_s[i] = src[i];
    for (int i = threadIdx.x; i < 4704; i += 512) {
        int oc = i / 147, r = i - oc * 147;
        w_s[r * 32 + oc] = w[i];
    }
    __syncthreads();

    const int tid = threadIdx.x;
    const int oc0 = (tid >> 7) * 8;
    const int pt  = tid & 127;
    float bv[8];
#pragma unroll
    for (int o = 0; o < 8; ++o) bv[o] = bia[oc0 + o];

    for (int it = 0; it < 4; ++it) {
        int seg = pt + 128 * it;
        bool valid = (seg < 507);
        int oy = seg / 13;
        int x0 = 3 * (seg - oy * 13);
        int ibase = valid ? (oy * 168 + 2 * x0) : 0;

        float2 acc2[3][4];
#pragma unroll
        for (int xi = 0; xi < 3; ++xi)
#pragma unroll
            for (int q = 0; q < 4; ++q) acc2[xi][q] = make_float2(0.f, 0.f);

#pragma unroll 1
        for (int c = 0; c < 3; ++c)
#pragma unroll 1
            for (int ky = 0; ky < 7; ++ky) {
                const float* ip = in_s + c * 7056 + ky * 84 + ibase;
                float iv[13];
#pragma unroll
                for (int o = 0; o < 13; ++o) iv[o] = ip[o];
#pragma unroll
                for (int kx = 0; kx < 7; ++kx) {
                    const float4* wp = (const float4*)(w_s + (c * 49 + ky * 7 + kx) * 32 + oc0);
                    float4 wa = wp[0], wb = wp[1];
                    float2 w01 = make_float2(wa.x, wa.y);
                    float2 w23 = make_float2(wa.z, wa.w);
                    float2 w45 = make_float2(wb.x, wb.y);
                    float2 w67 = make_float2(wb.z, wb.w);
#pragma unroll
                    for (int xi = 0; xi < 3; ++xi) {
                        float2 iv2 = make_float2(iv[kx + 2 * xi], iv[kx + 2 * xi]);
                        fma2(acc2[xi][0], iv2, w01);
                        fma2(acc2[xi][1], iv2, w23);
                        fma2(acc2[xi][2], iv2, w45);
                        fma2(acc2[xi][3], iv2, w67);
                    }
                }
            }
        if (valid) {
#pragma unroll
            for (int xi = 0; xi < 3; ++xi) {
                int p = oy * 39 + x0 + xi;
#pragma unroll
                for (int q = 0; q < 4; ++q) {
                    g_x1[((size_t)n * 32 + oc0 + 2 * q + 0) * 1521 + p] =
                        fmaxf(acc2[xi][q].x + bv[2 * q + 0], 0.f);
                    g_x1[((size_t)n * 32 + oc0 + 2 * q + 1) * 1521 + p] =
                        fmaxf(acc2[xi][q].y + bv[2 * q + 1], 0.f);
                }
            }
        }
    }
}

// ---------------------------------------------------------------------------
// conv2: [2048,32,39,39] -> [2048,64,18,18], 5x5 s2, ReLU. 512 threads.
// cp.async double-buffered channel chunks. Thread tile: 16 oc x 3 consecutive-x
// outputs with kx register-sliding window (9-float input window per (c,ky)).
// Rows of 18 = 6 segments of 3; 108 segments (pt < 108 valid).
// ---------------------------------------------------------------------------
__global__ __launch_bounds__(512, 1) void conv2_k(const float* __restrict__ bia) {
    extern __shared__ float sm[];
    float* in_b[2] = { sm, sm + 12168 };
    float* w_b[2]  = { sm + 24336, sm + 24336 + 12800 };
    const int n = blockIdx.x;
    const int tid = threadIdx.x;
    const int oc0 = (tid >> 7) * 16;
    const int pt  = tid & 127;
    const bool valid = (pt < 108);
    const int oy = pt / 6;
    const int x0 = 3 * (pt - oy * 6);
    const int ibase = valid ? (oy * 78 + 2 * x0) : 0;

    {
        const float4* srcI = (const float4*)(g_x1 + (size_t)n * 48672);
        const float4* srcW = (const float4*)(g_w2t);
        float4* dI = (float4*)in_b[0];
        float4* dW = (float4*)w_b[0];
        for (int i = tid; i < 3042; i += 512) cpa16(dI + i, srcI + i);
        for (int i = tid; i < 3200; i += 512) cpa16(dW + i, srcW + i);
        cpa_commit();
    }

    float2 acc2[3][8];
#pragma unroll
    for (int xi = 0; xi < 3; ++xi)
#pragma unroll
        for (int o = 0; o < 8; ++o) acc2[xi][o] = make_float2(0.f, 0.f);

    for (int cc = 0; cc < 4; ++cc) {
        cpa_wait0();
        __syncthreads();
        if (cc < 3) {
            const float4* srcI = (const float4*)(g_x1 + (size_t)n * 48672 + (cc + 1) * 12168);
            const float4* srcW = (const float4*)(g_w2t + (cc + 1) * 12800);
            float4* dI = (float4*)in_b[(cc + 1) & 1];
            float4* dW = (float4*)w_b[(cc + 1) & 1];
            for (int i = tid; i < 3042; i += 512) cpa16(dI + i, srcI + i);
            for (int i = tid; i < 3200; i += 512) cpa16(dW + i, srcW + i);
            cpa_commit();
        }
        const float* in_s = in_b[cc & 1];
        const float* w_s  = w_b[cc & 1];
#pragma unroll 1
        for (int c8 = 0; c8 < 8; ++c8)
#pragma unroll 1
            for (int ky = 0; ky < 5; ++ky) {
                const float* ip = in_s + c8 * 1521 + ky * 39 + ibase;
                float iv[9];
#pragma unroll
                for (int o = 0; o < 9; ++o) iv[o] = ip[o];
#pragma unroll
                for (int kx = 0; kx < 5; ++kx) {
                    const float4* wp = (const float4*)(w_s + (c8 * 25 + ky * 5 + kx) * 64 + oc0);
                    float4 q0 = wp[0], q1 = wp[1], q2 = wp[2], q3 = wp[3];
                    float2 wv[8];
                    wv[0] = make_float2(q0.x, q0.y); wv[1] = make_float2(q0.z, q0.w);
                    wv[2] = make_float2(q1.x, q1.y); wv[3] = make_float2(q1.z, q1.w);
                    wv[4] = make_float2(q2.x, q2.y); wv[5] = make_float2(q2.z, q2.w);
                    wv[6] = make_float2(q3.x, q3.y); wv[7] = make_float2(q3.z, q3.w);
#pragma unroll
                    for (int xi = 0; xi < 3; ++xi) {
                        float2 iv2 = make_float2(iv[kx + 2 * xi], iv[kx + 2 * xi]);
#pragma unroll
                        for (int o = 0; o < 8; ++o) fma2(acc2[xi][o], iv2, wv[o]);
                    }
                }
            }
        __syncthreads();
    }
    float bv[16];
#pragma unroll
    for (int o = 0; o < 16; ++o) bv[o] = bia[oc0 + o];
    if (valid) {
#pragma unroll
        for (int xi = 0; xi < 3; ++xi) {
            int p = oy * 18 + x0 + xi;
#pragma unroll
            for (int q = 0; q < 8; ++q) {
                g_x2[((size_t)n * 64 + oc0 + 2 * q + 0) * 324 + p] =
                    fmaxf(acc2[xi][q].x + bv[2 * q + 0], 0.f);
                g_x2[((size_t)n * 64 + oc0 + 2 * q + 1) * 324 + p] =
                    fmaxf(acc2[xi][q].y + bv[2 * q + 1], 0.f);
            }
        }
    }
}

// ---------------------------------------------------------------------------
// conv3: [2048,64,18,18] -> feat [2048,4096], 3x3 s2, ReLU.
// Block = 2 images, 256 threads (128/image). Thread tile = 8 oc x 4 pos.
// K chunked (8 chunks x 8 channels), cp.async double-buffered.
// ---------------------------------------------------------------------------
__global__ __launch_bounds__(256, 2) void conv3_k(const float* __restrict__ bia) {
    extern __shared__ float sm[];
    float* w_b[2]  = { sm, sm + 4608 };
    float* in_b[2] = { sm + 9216, sm + 9216 + 5184 };
    const int tid = threadIdx.x;
    const int img = tid >> 7;
    const int n0 = blockIdx.x * 2;
    const int hid = tid & 127;
    const int oc0 = (hid >> 4) * 8;
    const int posg = hid & 15;

    int ib[4];
#pragma unroll
    for (int j = 0; j < 4; ++j) {
        int p = posg * 4 + j;
        ib[j] = (p >> 3) * 36 + (p & 7) * 2;
    }

    {
        const float4* srcW  = (const float4*)(g_w3t);
        const float4* srcI0 = (const float4*)(g_x2 + (size_t)n0 * 20736);
        const float4* srcI1 = (const float4*)(g_x2 + (size_t)(n0 + 1) * 20736);
        float4* dW = (float4*)w_b[0];
        float4* dI = (float4*)in_b[0];
        for (int i = tid; i < 1152; i += 256) cpa16(dW + i, srcW + i);
        for (int i = tid; i < 648; i += 256) {
            cpa16(dI + i, srcI0 + i);
            cpa16(dI + 648 + i, srcI1 + i);
        }
        cpa_commit();
    }

    float2 acc2[4][4];
#pragma unroll
    for (int j = 0; j < 4; ++j)
#pragma unroll
        for (int q = 0; q < 4; ++q) acc2[j][q] = make_float2(0.f, 0.f);

    for (int cc = 0; cc < 8; ++cc) {
        cpa_wait0();
        __syncthreads();
        if (cc < 7) {
            const float4* srcW  = (const float4*)(g_w3t + (cc + 1) * 4608);
            const float4* srcI0 = (const float4*)(g_x2 + (size_t)n0 * 20736 + (cc + 1) * 2592);
            const float4* srcI1 = (const float4*)(g_x2 + (size_t)(n0 + 1) * 20736 + (cc + 1) * 2592);
            float4* dW = (float4*)w_b[(cc + 1) & 1];
            float4* dI = (float4*)in_b[(cc + 1) & 1];
            for (int i = tid; i < 1152; i += 256) cpa16(dW + i, srcW + i);
            for (int i = tid; i < 648; i += 256) {
                cpa16(dI + i, srcI0 + i);
                cpa16(dI + 648 + i, srcI1 + i);
            }
            cpa_commit();
        }
        const float* w_s  = w_b[cc & 1];
        const float* in_s = in_b[cc & 1] + img * 2592;
#pragma unroll 1
        for (int c8 = 0; c8 < 8; ++c8) {
#pragma unroll
            for (int ky = 0; ky < 3; ++ky)
#pragma unroll
                for (int kx = 0; kx < 3; ++kx) {
                    const float4* wp = (const float4*)(w_s + (c8 * 9 + ky * 3 + kx) * 64 + oc0);
                    float4 wa = wp[0], wb = wp[1];
                    float2 w01 = make_float2(wa.x, wa.y);
                    float2 w23 = make_float2(wa.z, wa.w);
                    float2 w45 = make_float2(wb.x, wb.y);
                    float2 w67 = make_float2(wb.z, wb.w);
                    const float* ip = in_s + c8 * 324 + ky * 18 + kx;
#pragma unroll
                    for (int j = 0; j < 4; ++j) {
                        float iv = ip[ib[j]];
                        float2 iv2 = make_float2(iv, iv);
                        fma2(acc2[j][0], iv2, w01);
                        fma2(acc2[j][1], iv2, w23);
                        fma2(acc2[j][2], iv2, w45);
                        fma2(acc2[j][3], iv2, w67);
                    }
                }
        }
    }

    float* dst = g_feat + (size_t)(n0 + img) * 4096;
    float bv[8];
#pragma unroll
    for (int o = 0; o < 8; ++o) bv[o] = bia[oc0 + o];
#pragma unroll
    for (int j = 0; j < 4; ++j) {
        int p = posg * 4 + j;
#pragma unroll
        for (int q = 0; q < 4; ++q) {
            dst[(oc0 + 2 * q + 0) * 64 + p] = fmaxf(acc2[j][q].x + bv[2 * q + 0], 0.f);
            dst[(oc0 + 2 * q + 1) * 64 + p] = fmaxf(acc2[j][q].y + bv[2 * q + 1], 0.f);
        }
    }
}

// ---------------------------------------------------------------------------
// Fused projection GEMM: 128x64 tiles, 256 threads, 8x4/thread, double-buffered.
// ---------------------------------------------------------------------------
__global__ __launch_bounds__(256, 1) void proj_k(const float* __restrict__ feat,
                                                 const float* __restrict__ wkey,
                                                 const float* __restrict__ wval,
                                                 const float* __restrict__ wih,
                                                 const float* __restrict__ bih,
                                                 float* __restrict__ keys,
                                                 float* __restrict__ vals,
                                                 float* __restrict__ gif) {
    __shared__ float As[2][16][132];
    __shared__ float Bs[2][16][68];
    const int tid = threadIdx.x;
    const int bx = blockIdx.x;
    const int m0 = blockIdx.y * 128;

    const float* Bw; int ldb; float* C; int ldc; int cn0; const float* bias = nullptr;
    if (bx < 4)      { cn0 = bx * 64;        Bw = wkey + (size_t)cn0 * 4096; ldb = 4096; C = keys; ldc = 256; }
    else if (bx < 8) { cn0 = (bx - 4) * 64;  Bw = wval + (size_t)cn0 * 4096; ldb = 4096; C = vals; ldc = 256; }
    else             { cn0 = (bx - 8) * 64;  Bw = wih  + (size_t)cn0 * 4352; ldb = 4352; C = gif;  ldc = 768;
                       bias = bih + cn0; }

    const int lrA = tid >> 1;
    const int lkA = (tid & 1) * 8;
    const int lrB = tid & 63;
    const int lkB = (tid >> 6) * 4;
    const float* aP = feat + (size_t)(m0 + lrA) * 4096 + lkA;
    const float* bP = Bw + (size_t)lrB * ldb + lkB;
    const int tx = tid & 15, ty = tid >> 4;

    float2 acc[8][2];
#pragma unroll
    for (int i = 0; i < 8; ++i) { acc[i][0] = make_float2(0.f, 0.f); acc[i][1] = make_float2(0.f, 0.f); }

    float4 a0 = *(const float4*)(aP);
    float4 a1 = *(const float4*)(aP + 4);
    float4 b0 = *(const float4*)(bP);
    As[0][lkA + 0][lrA] = a0.x; As[0][lkA + 1][lrA] = a0.y;
    As[0][lkA + 2][lrA] = a0.z; As[0][lkA + 3][lrA] = a0.w;
    As[0][lkA + 4][lrA] = a1.x; As[0][lkA + 5][lrA] = a1.y;
    As[0][lkA + 6][lrA] = a1.z; As[0][lkA + 7][lrA] = a1.w;
    Bs[0][lkB + 0][lrB] = b0.x; Bs[0][lkB + 1][lrB] = b0.y;
    Bs[0][lkB + 2][lrB] = b0.z; Bs[0][lkB + 3][lrB] = b0.w;
    __syncthreads();

    int st = 0;
    for (int k0 = 16; k0 < 4096; k0 += 16) {
        a0 = *(const float4*)(aP + k0);
        a1 = *(const float4*)(aP + k0 + 4);
        b0 = *(const float4*)(bP + k0);
#pragma unroll
        for (int kk = 0; kk < 16; ++kk) {
            float4 af0 = *(const float4*)(&As[st][kk][ty * 8]);
            float4 af1 = *(const float4*)(&As[st][kk][ty * 8 + 4]);
            float4 bf  = *(const float4*)(&Bs[st][kk][tx * 4]);
            float av[8] = {af0.x, af0.y, af0.z, af0.w, af1.x, af1.y, af1.z, af1.w};
            float2 bb0 = make_float2(bf.x, bf.y), bb1 = make_float2(bf.z, bf.w);
#pragma unroll
            for (int i = 0; i < 8; ++i) {
                float2 a2 = make_float2(av[i], av[i]);
                fma2(acc[i][0], a2, bb0);
                fma2(acc[i][1], a2, bb1);
            }
        }
        int ns = st ^ 1;
        As[ns][lkA + 0][lrA] = a0.x; As[ns][lkA + 1][lrA] = a0.y;
        As[ns][lkA + 2][lrA] = a0.z; As[ns][lkA + 3][lrA] = a0.w;
        As[ns][lkA + 4][lrA] = a1.x; As[ns][lkA + 5][lrA] = a1.y;
        As[ns][lkA + 6][lrA] = a1.z; As[ns][lkA + 7][lrA] = a1.w;
        Bs[ns][lkB + 0][lrB] = b0.x; Bs[ns][lkB + 1][lrB] = b0.y;
        Bs[ns][lkB + 2][lrB] = b0.z; Bs[ns][lkB + 3][lrB] = b0.w;
        __syncthreads();
        st = ns;
    }
#pragma unroll
    for (int kk = 0; kk < 16; ++kk) {
        float4 af0 = *(const float4*)(&As[st][kk][ty * 8]);
        float4 af1 = *(const float4*)(&As[st][kk][ty * 8 + 4]);
        float4 bf  = *(const float4*)(&Bs[st][kk][tx * 4]);
        float av[8] = {af0.x, af0.y, af0.z, af0.w, af1.x, af1.y, af1.z, af1.w};
        float2 bb0 = make_float2(bf.x, bf.y), bb1 = make_float2(bf.z, bf.w);
#pragma unroll
        for (int i = 0; i < 8; ++i) {
            float2 a2 = make_float2(av[i], av[i]);
            fma2(acc[i][0], a2, bb0);
            fma2(acc[i][1], a2, bb1);
        }
    }

    float bload[4] = {0.f, 0.f, 0.f, 0.f};
    if (bias) {
#pragma unroll
        for (int q = 0; q < 4; ++q) bload[q] = bias[tx * 4 + q];
    }
#pragma unroll
    for (int i = 0; i < 8; ++i) {
        int m = m0 + ty * 8 + i;
        float4 v;
        v.x = acc[i][0].x + bload[0]; v.y = acc[i][0].y + bload[1];
        v.z = acc[i][1].x + bload[2]; v.w = acc[i][1].y + bload[3];
        *(float4*)(C + (size_t)m * ldc + cn0 + tx * 4) = v;
    }
}

// ---------------------------------------------------------------------------
// Generic GEMM (whid GEMM): C = A*B^T (+bias)(+addm)(relu)
// ---------------------------------------------------------------------------
__global__ __launch_bounds__(256, 1) void gemm_k(const float* __restrict__ A,
                                                 const float* __restrict__ B,
                                                 float* __restrict__ C,
                                                 int M, int N, int K, int ldb,
                                                 const float* __restrict__ bias,
                                                 const float* __restrict__ addm,
                                                 int relu) {
    __shared__ float As[16][64];
    __shared__ float Bs[16][64];
    const int tid = threadIdx.x;
    const int m0 = blockIdx.y * 64, n0 = blockIdx.x * 64;
    const int lr = tid >> 2;
    const int lc = (tid & 3) * 4;
    const int tx = tid & 15, ty = tid >> 4;

    float2 acc2[4][2];
#pragma unroll
    for (int i = 0; i < 4; ++i) { acc2[i][0] = make_float2(0.f, 0.f); acc2[i][1] = make_float2(0.f, 0.f); }

    for (int k0 = 0; k0 < K; k0 += 16) {
        __syncthreads();
        float4 va = *(const float4*)(A + (size_t)(m0 + lr) * K + k0 + lc);
        float4 vb = *(const float4*)(B + (size_t)(n0 + lr) * ldb + k0 + lc);
        As[lc + 0][lr] = va.x; As[lc + 1][lr] = va.y;
        As[lc + 2][lr] = va.z; As[lc + 3][lr] = va.w;
        Bs[lc + 0][lr] = vb.x; Bs[lc + 1][lr] = vb.y;
        Bs[lc + 2][lr] = vb.z; Bs[lc + 3][lr] = vb.w;
        __syncthreads();
#pragma unroll
        for (int kk = 0; kk < 16; ++kk) {
            float4 a = *(const float4*)(&As[kk][ty * 4]);
            float4 b = *(const float4*)(&Bs[kk][tx * 4]);
            float2 b0 = make_float2(b.x, b.y), b1 = make_float2(b.z, b.w);
            float av[4] = {a.x, a.y, a.z, a.w};
#pragma unroll
            for (int i = 0; i < 4; ++i) {
                float2 a2 = make_float2(av[i], av[i]);
                fma2(acc2[i][0], a2, b0);
                fma2(acc2[i][1], a2, b1);
            }
        }
    }

#pragma unroll
    for (int i = 0; i < 4; ++i) {
        int m = m0 + ty * 4 + i;
        int nn = n0 + tx * 4;
        float4 v;
        v.x = acc2[i][0].x; v.y = acc2[i][0].y;
        v.z = acc2[i][1].x; v.w = acc2[i][1].y;
        if (bias) {
            v.x += bias[nn + 0]; v.y += bias[nn + 1];
            v.z += bias[nn + 2]; v.w += bias[nn + 3];
        }
        if (addm) {
            float4 ad = *(const float4*)(addm + (size_t)m * N + nn);
            v.x += ad.x; v.y += ad.y; v.z += ad.z; v.w += ad.w;
        }
        if (relu) {
            v.x = fmaxf(v.x, 0.f); v.y = fmaxf(v.y, 0.f);
            v.z = fmaxf(v.z, 0.f); v.w = fmaxf(v.w, 0.f);
        }
        *(float4*)(C + (size_t)m * N + nn) = v;
    }
}

// ---------------------------------------------------------------------------
// Sequential GRU + causal episodic attention scan (32 blocks, 512 threads).
// ---------------------------------------------------------------------------
__global__ __launch_bounds__(512, 1) void scan_k(const float* __restrict__ w_ih,
                                                 const float* __restrict__ w_hh,
                                                 const float* __restrict__ b_hh) {
    extern __shared__ float sm[];
    float* keys_s = sm;             // 16384
    float* vals_s = sm + 16384;     // 16384
    float* h_s    = sm + 32768;     // 256
    float* r_s    = sm + 33024;     // 256
    float* gi_s   = sm + 33280;     // 768
    float* gh_s   = sm + 34048;     // 768
    float* sc_s   = sm + 34816;     // 64
    float* red_s  = sm + 34880;     // 512

    const int b = blockIdx.x;
    const int tid = threadIdx.x;
    const int wid = tid >> 5, l = tid & 31;

    for (int i = tid; i < 16384; i += 512) {
        keys_s[i] = g_keys[(size_t)b * 16384 + i];
        vals_s[i] = g_vals[(size_t)b * 16384 + i];
    }
    if (tid < 256) { h_s[tid] = 0.f; r_s[tid] = 0.f; }
    __syncthreads();

    const float4* whh4 = (const float4*)w_hh;
    const float4* wih4 = (const float4*)w_ih;
    const float4* h4 = (const float4*)h_s;
    const float4* r4 = (const float4*)r_s;
    const float4* k4 = (const float4*)keys_s;

    for (int t = 0; t < 64; ++t) {
        const int n = b * 64 + t;

        float4 hh0 = h4[l], hh1 = h4[32 + l];
        float4 rr0 = r4[l], rr1 = r4[32 + l];
        float2 h2a = make_float2(hh0.x, hh0.y), h2b = make_float2(hh0.z, hh0.w);
        float2 h2c = make_float2(hh1.x, hh1.y), h2d = make_float2(hh1.z, hh1.w);
        float2 r2a = make_float2(rr0.x, rr0.y), r2b = make_float2(rr0.z, rr0.w);
        float2 r2c = make_float2(rr1.x, rr1.y), r2d = make_float2(rr1.z, rr1.w);
#pragma unroll 1
        for (int g = 0; g < 12; ++g) {
            float sh[4], sr[4];
#pragma unroll
            for (int u = 0; u < 4; ++u) {
                int j = wid + 16 * (g * 4 + u);
                const float4* wh = whh4 + (size_t)j * 64;
                const float4* wi = wih4 + (size_t)j * 1088 + 1024;
                float4 a0 = wh[l], a1 = wh[32 + l];
                float4 c0 = wi[l], c1 = wi[32 + l];
                float2 s2 = make_float2(0.f, 0.f), q2 = make_float2(0.f, 0.f);
                fma2(s2, h2a, make_float2(a0.x, a0.y));
                fma2(s2, h2b, make_float2(a0.z, a0.w));
                fma2(s2, h2c, make_float2(a1.x, a1.y));
                fma2(s2, h2d, make_float2(a1.z, a1.w));
                fma2(q2, r2a, make_float2(c0.x, c0.y));
                fma2(q2, r2b, make_float2(c0.z, c0.w));
                fma2(q2, r2c, make_float2(c1.x, c1.y));
                fma2(q2, r2d, make_float2(c1.z, c1.w));
                sh[u] = s2.x + s2.y;
                sr[u] = q2.x + q2.y;
            }
#pragma unroll
            for (int off = 16; off; off >>= 1) {
#pragma unroll
                for (int u = 0; u < 4; ++u) {
                    sh[u] += __shfl_down_sync(0xffffffffu, sh[u], off);
                    sr[u] += __shfl_down_sync(0xffffffffu, sr[u], off);
                }
            }
            if (l == 0) {
#pragma unroll
                for (int u = 0; u < 4; ++u) {
                    int j = wid + 16 * (g * 4 + u);
                    gh_s[j] = sh[u] + b_hh[j];
                    gi_s[j] = sr[u] + g_gif[(size_t)n * 768 + j];
                }
            }
        }
        __syncthreads();

        if (tid < 256) {
            int j = tid;
            float gr = gi_s[j] + gh_s[j];
            float gz = gi_s[256 + j] + gh_s[256 + j];
            float r = 1.f / (1.f + __expf(-gr));
            float z = 1.f / (1.f + __expf(-gz));
            float nn = tanhf(gi_s[512 + j] + r * gh_s[512 + j]);
            float h = (1.f - z) * nn + z * h_s[j];
            h_s[j] = h;
            g_hseq[(size_t)n * 256 + j] = h;
        }
        __syncthreads();

        for (int s = wid; s <= t; s += 16) {
            const float4* kp = k4 + (size_t)s * 64;
            float4 k0 = kp[l], k1 = kp[32 + l];
            float4 hb0 = h4[l], hb1 = h4[32 + l];
            float2 d2 = make_float2(0.f, 0.f);
            fma2(d2, make_float2(k0.x, k0.y), make_float2(hb0.x, hb0.y));
            fma2(d2, make_float2(k0.z, k0.w), make_float2(hb0.z, hb0.w));
            fma2(d2, make_float2(k1.x, k1.y), make_float2(hb1.x, hb1.y));
            fma2(d2, make_float2(k1.z, k1.w), make_float2(hb1.z, hb1.w));
            float d = d2.x + d2.y;
#pragma unroll
            for (int off = 16; off; off >>= 1) d += __shfl_down_sync(0xffffffffu, d, off);
            if (l == 0) sc_s[s] = d;
        }
        __syncthreads();

        if (wid == 0) {
            float v0 = (l <= t) ? sc_s[l] : -1e30f;
            float v1 = (l + 32 <= t) ? sc_s[l + 32] : -1e30f;
            float m = fmaxf(v0, v1);
#pragma unroll
            for (int off = 16; off; off >>= 1) m = fmaxf(m, __shfl_xor_sync(0xffffffffu, m, off));
            float e0 = (l <= t) ? __expf(v0 - m) : 0.f;
            float e1 = (l + 32 <= t) ? __expf(v1 - m) : 0.f;
            float ssum = e0 + e1;
#pragma unroll
            for (int off = 16; off; off >>= 1) ssum += __shfl_xor_sync(0xffffffffu, ssum, off);
            float inv = 1.f / ssum;
            sc_s[l] = e0 * inv;
            sc_s[l + 32] = e1 * inv;
        }
        __syncthreads();

        {
            int k = tid & 255, q = tid >> 8;
            float acc = 0.f;
            for (int s = q; s <= t; s += 2) acc += sc_s[s] * vals_s[s * 256 + k];
            red_s[tid] = acc;
        }
        __syncthreads();
        if (tid < 256) {
            float v = red_s[tid] + red_s[tid + 256];
            r_s[tid] = v;
            g_oseq[(size_t)n * 256 + tid] = v;
        }
        __syncthreads();
    }
}

// ---------------------------------------------------------------------------
// Dueling heads
// ---------------------------------------------------------------------------
__global__ __launch_bounds__(128, 8) void heads_k(const float* __restrict__ adv_w,
                                                  const float* __restrict__ adv_b,
                                                  const float* __restrict__ val_w,
                                                  const float* __restrict__ val_b,
                                                  float* __restrict__ out) {
    const int wid = threadIdx.x >> 5, l = threadIdx.x & 31;
    const int n = blockIdx.x * 4 + wid;
    const float4* gp = (const float4*)(g_gbuf + (size_t)n * 256);
    float4 g0 = gp[l], g1 = gp[l + 32];
    float res[7];
#pragma unroll
    for (int a = 0; a < 7; ++a) {
        const float* wr = (a < 6) ? (adv_w + a * 256) : val_w;
        const float4* wp = (const float4*)wr;
        float4 w0 = wp[l], w1 = wp[l + 32];
        float d = g0.x * w0.x + g0.y * w0.y + g0.z * w0.z + g0.w * w0.w
                + g1.x * w1.x + g1.y * w1.y + g1.z * w1.z + g1.w * w1.w;
#pragma unroll
        for (int off = 16; off; off >>= 1) d += __shfl_down_sync(0xffffffffu, d, off);
        res[a] = d;
    }
    if (l == 0) {
        float adv[6], s = 0.f;
#pragma unroll
        for (int a = 0; a < 6; ++a) { adv[a] = res[a] + adv_b[a]; s += adv[a]; }
        float v = res[6] + val_b[0];
        float mean = s * (1.f / 6.f);
#pragma unroll
        for (int a = 0; a < 6; ++a) out[n * 6 + a] = v + adv[a] - mean;
    }
}

// ---------------------------------------------------------------------------
extern "C" void kernel_launch(void* const* d_in, const int* in_sizes, int n_in,
                              void* d_out, int out_size) {
    const float* obs  = (const float*)d_in[0];
    const float* c1w  = (const float*)d_in[1];
    const float* c1b  = (const float*)d_in[2];
    const float* c2w  = (const float*)d_in[3];
    const float* c2b  = (const float*)d_in[4];
    const float* c3w  = (const float*)d_in[5];
    const float* c3b  = (const float*)d_in[6];
    const float* wkey = (const float*)d_in[7];
    const float* wval = (const float*)d_in[8];
    const float* wih  = (const float*)d_in[9];
    const float* whh  = (const float*)d_in[10];
    const float* bih  = (const float*)d_in[11];
    const float* bhh  = (const float*)d_in[12];
    const float* whid = (const float*)d_in[13];
    const float* advw = (const float*)d_in[14];
    const float* advb = (const float*)d_in[15];
    const float* valw = (const float*)d_in[16];
    const float* valb = (const float*)d_in[17];
    float* out = (float*)d_out;

    (void)in_sizes; (void)n_in; (void)out_size;

    cudaFuncSetAttribute(conv1_k, cudaFuncAttributeMaxDynamicSharedMemorySize, 25872 * 4);
    cudaFuncSetAttribute(conv2_k, cudaFuncAttributeMaxDynamicSharedMemorySize, 49936 * 4);
    cudaFuncSetAttribute(conv3_k, cudaFuncAttributeMaxDynamicSharedMemorySize, 19584 * 4);
    cudaFuncSetAttribute(scan_k,  cudaFuncAttributeMaxDynamicSharedMemorySize, 35392 * 4);

    void *p_feat, *p_keys, *p_vals, *p_gif, *p_hseq, *p_oseq, *p_gbuf;
    cudaGetSymbolAddress(&p_feat, g_feat);
    cudaGetSymbolAddress(&p_keys, g_keys);
    cudaGetSymbolAddress(&p_vals, g_vals);
    cudaGetSymbolAddress(&p_gif,  g_gif);
    cudaGetSymbolAddress(&p_hseq, g_hseq);
    cudaGetSymbolAddress(&p_oseq, g_oseq);
    cudaGetSymbolAddress(&p_gbuf, g_gbuf);

    w2t_k<<<200, 256>>>(c2w);
    w3t_k<<<144, 256>>>(c3w);

    conv1_k<<<2048, 512, 25872 * 4>>>(obs, c1w, c1b);
    conv2_k<<<2048, 512, 49936 * 4>>>(c2b);
    conv3_k<<<1024, 256, 19584 * 4>>>(c3b);

    proj_k<<<dim3(20, 16), 256>>>((const float*)p_feat, wkey, wval, wih, bih,
                                  (float*)p_keys, (float*)p_vals, (float*)p_gif);

    scan_k<<<32, 512, 35392 * 4>>>(wih, whh, bhh);

    gemm_k<<<dim3(4, 32), 256>>>((const float*)p_hseq, whid, (float*)p_gbuf,
                                 2048, 256, 256, 256, nullptr, (const float*)p_oseq, 1);

    heads_k<<<512, 128>>>(advw, advb, valw, valb, out);
}

// round 12
// speedup vs baseline: 1.0658x; 1.0658x over previous
#include <cuda_runtime.h>
#include <cstdint>
#include <cstddef>

// ---------------------------------------------------------------------------
// Packed fp32x2 FMA (sm_103a): 2 independent fp32 MACs per instruction.
// ---------------------------------------------------------------------------
__device__ __forceinline__ void fma2(float2 &c, const float2 a, const float2 b) {
    asm("fma.rn.f32x2 %0, %1, %2, %0;"
        : "+l"(reinterpret_cast<unsigned long long &>(c))
        : "l"(reinterpret_cast<const unsigned long long &>(const_cast<float2 &>(a))),
          "l"(reinterpret_cast<const unsigned long long &>(const_cast<float2 &>(b))));
}

// cp.async helpers (16B)
__device__ __forceinline__ void cpa16(void* s, const void* g) {
    unsigned saddr = (unsigned)__cvta_generic_to_shared(s);
    asm volatile("cp.async.cg.shared.global [%0], [%1], 16;\n" :: "r"(saddr), "l"(g));
}
__device__ __forceinline__ void cpa_commit() { asm volatile("cp.async.commit_group;\n"); }
__device__ __forceinline__ void cpa_wait0()  { asm volatile("cp.async.wait_group 0;\n"); }

// ---------------------------------------------------------------------------
// Scratch (device globals; allocation-free contract)
// ---------------------------------------------------------------------------
__device__ __align__(16) float g_x1[2048u * 32u * 1521u];   // conv1 out
__device__ __align__(16) float g_x2[2048u * 64u * 324u];    // conv2 out
__device__ __align__(16) float g_feat[2048u * 4096u];       // conv3 out / flattened
__device__ __align__(16) float g_keys[2048u * 256u];
__device__ __align__(16) float g_vals[2048u * 256u];
__device__ __align__(16) float g_gif[2048u * 768u];         // feat-part of GRU gi (+b_ih)
__device__ __align__(16) float g_hseq[2048u * 256u];
__device__ __align__(16) float g_oseq[2048u * 256u];
__device__ __align__(16) float g_gbuf[2048u * 256u];        // relu(hseq@Wh^T + oseq)
__device__ __align__(16) float g_w2t[800u * 64u];           // conv2 weights transposed [r][oc]
__device__ __align__(16) float g_w3t[576u * 64u];           // conv3 weights transposed [r][oc]

// ---------------------------------------------------------------------------
// weight transposes (oc-contiguous)
// ---------------------------------------------------------------------------
__global__ void w2t_k(const float* __restrict__ w) {
    int i = blockIdx.x * 256 + threadIdx.x;   // 51200
    if (i < 51200) {
        int r = i >> 6, oc = i & 63;
        g_w2t[i] = w[oc * 800 + r];
    }
}
__global__ void w3t_k(const float* __restrict__ w) {
    int i = blockIdx.x * 256 + threadIdx.x;   // 36864
    if (i < 36864) {
        int r = i >> 6, oc = i & 63;
        g_w3t[i] = w[oc * 576 + r];
    }
}

// ---------------------------------------------------------------------------
// conv1: [2048,3,84,84] -> [2048,32,39,39], 7x7 s2, ReLU. 512 threads.
// Thread tile: 8 oc x 3 consecutive-x outputs; kx register-sliding window
// loaded via 6xLDS.64 + 1 scalar (window base always even here).
// ---------------------------------------------------------------------------
__global__ __launch_bounds__(512, 1) void conv1_k(const float* __restrict__ obs,
                                                  const float* __restrict__ w,
                                                  const float* __restrict__ bia) {
    extern __shared__ float sm[];
    float* in_s = sm;            // 21168
    float* w_s  = sm + 21168;    // 4704
    const int n = blockIdx.x;
    const float* src = obs + (size_t)n * 21168;
    for (int i = threadIdx.x; i < 21168; i += 512) in_s[i] = src[i];
    for (int i = threadIdx.x; i < 4704; i += 512) {
        int oc = i / 147, r = i - oc * 147;
        w_s[r * 32 + oc] = w[i];
    }
    __syncthreads();

    const int tid = threadIdx.x;
    const int oc0 = (tid >> 7) * 8;
    const int pt  = tid & 127;
    float bv[8];
#pragma unroll
    for (int o = 0; o < 8; ++o) bv[o] = bia[oc0 + o];

    for (int it = 0; it < 4; ++it) {
        int seg = pt + 128 * it;
        bool valid = (seg < 507);
        int oy = seg / 13;
        int x0 = 3 * (seg - oy * 13);
        int ibase = valid ? (oy * 168 + 2 * x0) : 0;   // always even

        float2 acc2[3][4];
#pragma unroll
        for (int xi = 0; xi < 3; ++xi)
#pragma unroll
            for (int q = 0; q < 4; ++q) acc2[xi][q] = make_float2(0.f, 0.f);

#pragma unroll 1
        for (int c = 0; c < 3; ++c)
#pragma unroll 1
            for (int ky = 0; ky < 7; ++ky) {
                // c*7056 and ky*84 are even; ibase even -> float2-aligned
                const float* ip = in_s + c * 7056 + ky * 84 + ibase;
                const float2* ip2 = (const float2*)ip;
                float iv[13];
                float2 t0 = ip2[0], t1 = ip2[1], t2 = ip2[2];
                float2 t3 = ip2[3], t4 = ip2[4], t5 = ip2[5];
                iv[0] = t0.x; iv[1] = t0.y; iv[2] = t1.x; iv[3] = t1.y;
                iv[4] = t2.x; iv[5] = t2.y; iv[6] = t3.x; iv[7] = t3.y;
                iv[8] = t4.x; iv[9] = t4.y; iv[10] = t5.x; iv[11] = t5.y;
                iv[12] = ip[12];
#pragma unroll
                for (int kx = 0; kx < 7; ++kx) {
                    const float4* wp = (const float4*)(w_s + (c * 49 + ky * 7 + kx) * 32 + oc0);
                    float4 wa = wp[0], wb = wp[1];
                    float2 w01 = make_float2(wa.x, wa.y);
                    float2 w23 = make_float2(wa.z, wa.w);
                    float2 w45 = make_float2(wb.x, wb.y);
                    float2 w67 = make_float2(wb.z, wb.w);
#pragma unroll
                    for (int xi = 0; xi < 3; ++xi) {
                        float2 iv2 = make_float2(iv[kx + 2 * xi], iv[kx + 2 * xi]);
                        fma2(acc2[xi][0], iv2, w01);
                        fma2(acc2[xi][1], iv2, w23);
                        fma2(acc2[xi][2], iv2, w45);
                        fma2(acc2[xi][3], iv2, w67);
                    }
                }
            }
        if (valid) {
#pragma unroll
            for (int xi = 0; xi < 3; ++xi) {
                int p = oy * 39 + x0 + xi;
#pragma unroll
                for (int q = 0; q < 4; ++q) {
                    g_x1[((size_t)n * 32 + oc0 + 2 * q + 0) * 1521 + p] =
                        fmaxf(acc2[xi][q].x + bv[2 * q + 0], 0.f);
                    g_x1[((size_t)n * 32 + oc0 + 2 * q + 1) * 1521 + p] =
                        fmaxf(acc2[xi][q].y + bv[2 * q + 1], 0.f);
                }
            }
        }
    }
}

// ---------------------------------------------------------------------------
// conv2: [2048,32,39,39] -> [2048,64,18,18], 5x5 s2, ReLU. 512 threads.
// cp.async double-buffered channel chunks. Thread tile: 16 oc x 3 consecutive-x
// outputs; 9-float input window. Window offset parity = (c8*1521+ky*39)&1,
// UNIFORM across the block -> uniform branch selects aligned LDS.64 pattern.
// ---------------------------------------------------------------------------
__global__ __launch_bounds__(512, 1) void conv2_k(const float* __restrict__ bia) {
    extern __shared__ float sm[];
    float* in_b[2] = { sm, sm + 12168 };
    float* w_b[2]  = { sm + 24336, sm + 24336 + 12800 };
    const int n = blockIdx.x;
    const int tid = threadIdx.x;
    const int oc0 = (tid >> 7) * 16;
    const int pt  = tid & 127;
    const bool valid = (pt < 108);
    const int oy = pt / 6;
    const int x0 = 3 * (pt - oy * 6);
    const int ibase = valid ? (oy * 78 + 2 * x0) : 0;   // always even

    {
        const float4* srcI = (const float4*)(g_x1 + (size_t)n * 48672);
        const float4* srcW = (const float4*)(g_w2t);
        float4* dI = (float4*)in_b[0];
        float4* dW = (float4*)w_b[0];
        for (int i = tid; i < 3042; i += 512) cpa16(dI + i, srcI + i);
        for (int i = tid; i < 3200; i += 512) cpa16(dW + i, srcW + i);
        cpa_commit();
    }

    float2 acc2[3][8];
#pragma unroll
    for (int xi = 0; xi < 3; ++xi)
#pragma unroll
        for (int o = 0; o < 8; ++o) acc2[xi][o] = make_float2(0.f, 0.f);

    for (int cc = 0; cc < 4; ++cc) {
        cpa_wait0();
        __syncthreads();
        if (cc < 3) {
            const float4* srcI = (const float4*)(g_x1 + (size_t)n * 48672 + (cc + 1) * 12168);
            const float4* srcW = (const float4*)(g_w2t + (cc + 1) * 12800);
            float4* dI = (float4*)in_b[(cc + 1) & 1];
            float4* dW = (float4*)w_b[(cc + 1) & 1];
            for (int i = tid; i < 3042; i += 512) cpa16(dI + i, srcI + i);
            for (int i = tid; i < 3200; i += 512) cpa16(dW + i, srcW + i);
            cpa_commit();
        }
        const float* in_s = in_b[cc & 1];
        const float* w_s  = w_b[cc & 1];
#pragma unroll 1
        for (int c8 = 0; c8 < 8; ++c8)
#pragma unroll 1
            for (int ky = 0; ky < 5; ++ky) {
                const int woff = c8 * 1521 + ky * 39;      // parity uniform over block
                const float* ip = in_s + woff + ibase;
                float iv[9];
                if ((woff & 1) == 0) {
                    const float2* ip2 = (const float2*)ip;
                    float2 t0 = ip2[0], t1 = ip2[1], t2 = ip2[2], t3 = ip2[3];
                    iv[0] = t0.x; iv[1] = t0.y; iv[2] = t1.x; iv[3] = t1.y;
                    iv[4] = t2.x; iv[5] = t2.y; iv[6] = t3.x; iv[7] = t3.y;
                    iv[8] = ip[8];
                } else {
                    iv[0] = ip[0];
                    const float2* ip2 = (const float2*)(ip + 1);
                    float2 t0 = ip2[0], t1 = ip2[1], t2 = ip2[2], t3 = ip2[3];
                    iv[1] = t0.x; iv[2] = t0.y; iv[3] = t1.x; iv[4] = t1.y;
                    iv[5] = t2.x; iv[6] = t2.y; iv[7] = t3.x; iv[8] = t3.y;
                }
#pragma unroll
                for (int kx = 0; kx < 5; ++kx) {
                    const float4* wp = (const float4*)(w_s + (c8 * 25 + ky * 5 + kx) * 64 + oc0);
                    float4 q0 = wp[0], q1 = wp[1], q2 = wp[2], q3 = wp[3];
                    float2 wv[8];
                    wv[0] = make_float2(q0.x, q0.y); wv[1] = make_float2(q0.z, q0.w);
                    wv[2] = make_float2(q1.x, q1.y); wv[3] = make_float2(q1.z, q1.w);
                    wv[4] = make_float2(q2.x, q2.y); wv[5] = make_float2(q2.z, q2.w);
                    wv[6] = make_float2(q3.x, q3.y); wv[7] = make_float2(q3.z, q3.w);
#pragma unroll
                    for (int xi = 0; xi < 3; ++xi) {
                        float2 iv2 = make_float2(iv[kx + 2 * xi], iv[kx + 2 * xi]);
#pragma unroll
                        for (int o = 0; o < 8; ++o) fma2(acc2[xi][o], iv2, wv[o]);
                    }
                }
            }
        __syncthreads();
    }
    float bv[16];
#pragma unroll
    for (int o = 0; o < 16; ++o) bv[o] = bia[oc0 + o];
    if (valid) {
#pragma unroll
        for (int xi = 0; xi < 3; ++xi) {
            int p = oy * 18 + x0 + xi;
#pragma unroll
            for (int q = 0; q < 8; ++q) {
                g_x2[((size_t)n * 64 + oc0 + 2 * q + 0) * 324 + p] =
                    fmaxf(acc2[xi][q].x + bv[2 * q + 0], 0.f);
                g_x2[((size_t)n * 64 + oc0 + 2 * q + 1) * 324 + p] =
                    fmaxf(acc2[xi][q].y + bv[2 * q + 1], 0.f);
            }
        }
    }
}

// ---------------------------------------------------------------------------
// conv3: [2048,64,18,18] -> feat [2048,4096], 3x3 s2, ReLU.
// Block = 2 images, 256 threads (128/image). Thread tile = 8 oc x 4 pos.
// K chunked (8 chunks x 8 channels), cp.async double-buffered.
// ---------------------------------------------------------------------------
__global__ __launch_bounds__(256, 2) void conv3_k(const float* __restrict__ bia) {
    extern __shared__ float sm[];
    float* w_b[2]  = { sm, sm + 4608 };
    float* in_b[2] = { sm + 9216, sm + 9216 + 5184 };
    const int tid = threadIdx.x;
    const int img = tid >> 7;
    const int n0 = blockIdx.x * 2;
    const int hid = tid & 127;
    const int oc0 = (hid >> 4) * 8;
    const int posg = hid & 15;

    int ib[4];
#pragma unroll
    for (int j = 0; j < 4; ++j) {
        int p = posg * 4 + j;
        ib[j] = (p >> 3) * 36 + (p & 7) * 2;
    }

    {
        const float4* srcW  = (const float4*)(g_w3t);
        const float4* srcI0 = (const float4*)(g_x2 + (size_t)n0 * 20736);
        const float4* srcI1 = (const float4*)(g_x2 + (size_t)(n0 + 1) * 20736);
        float4* dW = (float4*)w_b[0];
        float4* dI = (float4*)in_b[0];
        for (int i = tid; i < 1152; i += 256) cpa16(dW + i, srcW + i);
        for (int i = tid; i < 648; i += 256) {
            cpa16(dI + i, srcI0 + i);
            cpa16(dI + 648 + i, srcI1 + i);
        }
        cpa_commit();
    }

    float2 acc2[4][4];
#pragma unroll
    for (int j = 0; j < 4; ++j)
#pragma unroll
        for (int q = 0; q < 4; ++q) acc2[j][q] = make_float2(0.f, 0.f);

    for (int cc = 0; cc < 8; ++cc) {
        cpa_wait0();
        __syncthreads();
        if (cc < 7) {
            const float4* srcW  = (const float4*)(g_w3t + (cc + 1) * 4608);
            const float4* srcI0 = (const float4*)(g_x2 + (size_t)n0 * 20736 + (cc + 1) * 2592);
            const float4* srcI1 = (const float4*)(g_x2 + (size_t)(n0 + 1) * 20736 + (cc + 1) * 2592);
            float4* dW = (float4*)w_b[(cc + 1) & 1];
            float4* dI = (float4*)in_b[(cc + 1) & 1];
            for (int i = tid; i < 1152; i += 256) cpa16(dW + i, srcW + i);
            for (int i = tid; i < 648; i += 256) {
                cpa16(dI + i, srcI0 + i);
                cpa16(dI + 648 + i, srcI1 + i);
            }
            cpa_commit();
        }
        const float* w_s  = w_b[cc & 1];
        const float* in_s = in_b[cc & 1] + img * 2592;
#pragma unroll 1
        for (int c8 = 0; c8 < 8; ++c8) {
#pragma unroll
            for (int ky = 0; ky < 3; ++ky)
#pragma unroll
                for (int kx = 0; kx < 3; ++kx) {
                    const float4* wp = (const float4*)(w_s + (c8 * 9 + ky * 3 + kx) * 64 + oc0);
                    float4 wa = wp[0], wb = wp[1];
                    float2 w01 = make_float2(wa.x, wa.y);
                    float2 w23 = make_float2(wa.z, wa.w);
                    float2 w45 = make_float2(wb.x, wb.y);
                    float2 w67 = make_float2(wb.z, wb.w);
                    const float* ip = in_s + c8 * 324 + ky * 18 + kx;
#pragma unroll
                    for (int j = 0; j < 4; ++j) {
                        float iv = ip[ib[j]];
                        float2 iv2 = make_float2(iv, iv);
                        fma2(acc2[j][0], iv2, w01);
                        fma2(acc2[j][1], iv2, w23);
                        fma2(acc2[j][2], iv2, w45);
                        fma2(acc2[j][3], iv2, w67);
                    }
                }
        }
    }

    float* dst = g_feat + (size_t)(n0 + img) * 4096;
    float bv[8];
#pragma unroll
    for (int o = 0; o < 8; ++o) bv[o] = bia[oc0 + o];
#pragma unroll
    for (int j = 0; j < 4; ++j) {
        int p = posg * 4 + j;
#pragma unroll
        for (int q = 0; q < 4; ++q) {
            dst[(oc0 + 2 * q + 0) * 64 + p] = fmaxf(acc2[j][q].x + bv[2 * q + 0], 0.f);
            dst[(oc0 + 2 * q + 1) * 64 + p] = fmaxf(acc2[j][q].y + bv[2 * q + 1], 0.f);
        }
    }
}

// ---------------------------------------------------------------------------
// Fused projection GEMM: 128x64 tiles, 256 threads, 8x4/thread, double-buffered.
// ---------------------------------------------------------------------------
__global__ __launch_bounds__(256, 1) void proj_k(const float* __restrict__ feat,
                                                 const float* __restrict__ wkey,
                                                 const float* __restrict__ wval,
                                                 const float* __restrict__ wih,
                                                 const float* __restrict__ bih,
                                                 float* __restrict__ keys,
                                                 float* __restrict__ vals,
                                                 float* __restrict__ gif) {
    __shared__ float As[2][16][132];
    __shared__ float Bs[2][16][68];
    const int tid = threadIdx.x;
    const int bx = blockIdx.x;
    const int m0 = blockIdx.y * 128;

    const float* Bw; int ldb; float* C; int ldc; int cn0; const float* bias = nullptr;
    if (bx < 4)      { cn0 = bx * 64;        Bw = wkey + (size_t)cn0 * 4096; ldb = 4096; C = keys; ldc = 256; }
    else if (bx < 8) { cn0 = (bx - 4) * 64;  Bw = wval + (size_t)cn0 * 4096; ldb = 4096; C = vals; ldc = 256; }
    else             { cn0 = (bx - 8) * 64;  Bw = wih  + (size_t)cn0 * 4352; ldb = 4352; C = gif;  ldc = 768;
                       bias = bih + cn0; }

    const int lrA = tid >> 1;
    const int lkA = (tid & 1) * 8;
    const int lrB = tid & 63;
    const int lkB = (tid >> 6) * 4;
    const float* aP = feat + (size_t)(m0 + lrA) * 4096 + lkA;
    const float* bP = Bw + (size_t)lrB * ldb + lkB;
    const int tx = tid & 15, ty = tid >> 4;

    float2 acc[8][2];
#pragma unroll
    for (int i = 0; i < 8; ++i) { acc[i][0] = make_float2(0.f, 0.f); acc[i][1] = make_float2(0.f, 0.f); }

    float4 a0 = *(const float4*)(aP);
    float4 a1 = *(const float4*)(aP + 4);
    float4 b0 = *(const float4*)(bP);
    As[0][lkA + 0][lrA] = a0.x; As[0][lkA + 1][lrA] = a0.y;
    As[0][lkA + 2][lrA] = a0.z; As[0][lkA + 3][lrA] = a0.w;
    As[0][lkA + 4][lrA] = a1.x; As[0][lkA + 5][lrA] = a1.y;
    As[0][lkA + 6][lrA] = a1.z; As[0][lkA + 7][lrA] = a1.w;
    Bs[0][lkB + 0][lrB] = b0.x; Bs[0][lkB + 1][lrB] = b0.y;
    Bs[0][lkB + 2][lrB] = b0.z; Bs[0][lkB + 3][lrB] = b0.w;
    __syncthreads();

    int st = 0;
    for (int k0 = 16; k0 < 4096; k0 += 16) {
        a0 = *(const float4*)(aP + k0);
        a1 = *(const float4*)(aP + k0 + 4);
        b0 = *(const float4*)(bP + k0);
#pragma unroll
        for (int kk = 0; kk < 16; ++kk) {
            float4 af0 = *(const float4*)(&As[st][kk][ty * 8]);
            float4 af1 = *(const float4*)(&As[st][kk][ty * 8 + 4]);
            float4 bf  = *(const float4*)(&Bs[st][kk][tx * 4]);
            float av[8] = {af0.x, af0.y, af0.z, af0.w, af1.x, af1.y, af1.z, af1.w};
            float2 bb0 = make_float2(bf.x, bf.y), bb1 = make_float2(bf.z, bf.w);
#pragma unroll
            for (int i = 0; i < 8; ++i) {
                float2 a2 = make_float2(av[i], av[i]);
                fma2(acc[i][0], a2, bb0);
                fma2(acc[i][1], a2, bb1);
            }
        }
        int ns = st ^ 1;
        As[ns][lkA + 0][lrA] = a0.x; As[ns][lkA + 1][lrA] = a0.y;
        As[ns][lkA + 2][lrA] = a0.z; As[ns][lkA + 3][lrA] = a0.w;
        As[ns][lkA + 4][lrA] = a1.x; As[ns][lkA + 5][lrA] = a1.y;
        As[ns][lkA + 6][lrA] = a1.z; As[ns][lkA + 7][lrA] = a1.w;
        Bs[ns][lkB + 0][lrB] = b0.x; Bs[ns][lkB + 1][lrB] = b0.y;
        Bs[ns][lkB + 2][lrB] = b0.z; Bs[ns][lkB + 3][lrB] = b0.w;
        __syncthreads();
        st = ns;
    }
#pragma unroll
    for (int kk = 0; kk < 16; ++kk) {
        float4 af0 = *(const float4*)(&As[st][kk][ty * 8]);
        float4 af1 = *(const float4*)(&As[st][kk][ty * 8 + 4]);
        float4 bf  = *(const float4*)(&Bs[st][kk][tx * 4]);
        float av[8] = {af0.x, af0.y, af0.z, af0.w, af1.x, af1.y, af1.z, af1.w};
        float2 bb0 = make_float2(bf.x, bf.y), bb1 = make_float2(bf.z, bf.w);
#pragma unroll
        for (int i = 0; i < 8; ++i) {
            float2 a2 = make_float2(av[i], av[i]);
            fma2(acc[i][0], a2, bb0);
            fma2(acc[i][1], a2, bb1);
        }
    }

    float bload[4] = {0.f, 0.f, 0.f, 0.f};
    if (bias) {
#pragma unroll
        for (int q = 0; q < 4; ++q) bload[q] = bias[tx * 4 + q];
    }
#pragma unroll
    for (int i = 0; i < 8; ++i) {
        int m = m0 + ty * 8 + i;
        float4 v;
        v.x = acc[i][0].x + bload[0]; v.y = acc[i][0].y + bload[1];
        v.z = acc[i][1].x + bload[2]; v.w = acc[i][1].y + bload[3];
        *(float4*)(C + (size_t)m * ldc + cn0 + tx * 4) = v;
    }
}

// ---------------------------------------------------------------------------
// Generic GEMM (whid GEMM): C = A*B^T (+bias)(+addm)(relu)
// ---------------------------------------------------------------------------
__global__ __launch_bounds__(256, 1) void gemm_k(const float* __restrict__ A,
                                                 const float* __restrict__ B,
                                                 float* __restrict__ C,
                                                 int M, int N, int K, int ldb,
                                                 const float* __restrict__ bias,
                                                 const float* __restrict__ addm,
                                                 int relu) {
    __shared__ float As[16][64];
    __shared__ float Bs[16][64];
    const int tid = threadIdx.x;
    const int m0 = blockIdx.y * 64, n0 = blockIdx.x * 64;
    const int lr = tid >> 2;
    const int lc = (tid & 3) * 4;
    const int tx = tid & 15, ty = tid >> 4;

    float2 acc2[4][2];
#pragma unroll
    for (int i = 0; i < 4; ++i) { acc2[i][0] = make_float2(0.f, 0.f); acc2[i][1] = make_float2(0.f, 0.f); }

    for (int k0 = 0; k0 < K; k0 += 16) {
        __syncthreads();
        float4 va = *(const float4*)(A + (size_t)(m0 + lr) * K + k0 + lc);
        float4 vb = *(const float4*)(B + (size_t)(n0 + lr) * ldb + k0 + lc);
        As[lc + 0][lr] = va.x; As[lc + 1][lr] = va.y;
        As[lc + 2][lr] = va.z; As[lc + 3][lr] = va.w;
        Bs[lc + 0][lr] = vb.x; Bs[lc + 1][lr] = vb.y;
        Bs[lc + 2][lr] = vb.z; Bs[lc + 3][lr] = vb.w;
        __syncthreads();
#pragma unroll
        for (int kk = 0; kk < 16; ++kk) {
            float4 a = *(const float4*)(&As[kk][ty * 4]);
            float4 b = *(const float4*)(&Bs[kk][tx * 4]);
            float2 b0 = make_float2(b.x, b.y), b1 = make_float2(b.z, b.w);
            float av[4] = {a.x, a.y, a.z, a.w};
#pragma unroll
            for (int i = 0; i < 4; ++i) {
                float2 a2 = make_float2(av[i], av[i]);
                fma2(acc2[i][0], a2, b0);
                fma2(acc2[i][1], a2, b1);
            }
        }
    }

#pragma unroll
    for (int i = 0; i < 4; ++i) {
        int m = m0 + ty * 4 + i;
        int nn = n0 + tx * 4;
        float4 v;
        v.x = acc2[i][0].x; v.y = acc2[i][0].y;
        v.z = acc2[i][1].x; v.w = acc2[i][1].y;
        if (bias) {
            v.x += bias[nn + 0]; v.y += bias[nn + 1];
            v.z += bias[nn + 2]; v.w += bias[nn + 3];
        }
        if (addm) {
            float4 ad = *(const float4*)(addm + (size_t)m * N + nn);
            v.x += ad.x; v.y += ad.y; v.z += ad.z; v.w += ad.w;
        }
        if (relu) {
            v.x = fmaxf(v.x, 0.f); v.y = fmaxf(v.y, 0.f);
            v.z = fmaxf(v.z, 0.f); v.w = fmaxf(v.w, 0.f);
        }
        *(float4*)(C + (size_t)m * N + nn) = v;
    }
}

// ---------------------------------------------------------------------------
// Sequential GRU + causal episodic attention scan (32 blocks, 512 threads).
// ---------------------------------------------------------------------------
__global__ __launch_bounds__(512, 1) void scan_k(const float* __restrict__ w_ih,
                                                 const float* __restrict__ w_hh,
                                                 const float* __restrict__ b_hh) {
    extern __shared__ float sm[];
    float* keys_s = sm;             // 16384
    float* vals_s = sm + 16384;     // 16384
    float* h_s    = sm + 32768;     // 256
    float* r_s    = sm + 33024;     // 256
    float* gi_s   = sm + 33280;     // 768
    float* gh_s   = sm + 34048;     // 768
    float* sc_s   = sm + 34816;     // 64
    float* red_s  = sm + 34880;     // 512

    const int b = blockIdx.x;
    const int tid = threadIdx.x;
    const int wid = tid >> 5, l = tid & 31;

    for (int i = tid; i < 16384; i += 512) {
        keys_s[i] = g_keys[(size_t)b * 16384 + i];
        vals_s[i] = g_vals[(size_t)b * 16384 + i];
    }
    if (tid < 256) { h_s[tid] = 0.f; r_s[tid] = 0.f; }
    __syncthreads();

    const float4* whh4 = (const float4*)w_hh;
    const float4* wih4 = (const float4*)w_ih;
    const float4* h4 = (const float4*)h_s;
    const float4* r4 = (const float4*)r_s;
    const float4* k4 = (const float4*)keys_s;

    for (int t = 0; t < 64; ++t) {
        const int n = b * 64 + t;

        float4 hh0 = h4[l], hh1 = h4[32 + l];
        float4 rr0 = r4[l], rr1 = r4[32 + l];
        float2 h2a = make_float2(hh0.x, hh0.y), h2b = make_float2(hh0.z, hh0.w);
        float2 h2c = make_float2(hh1.x, hh1.y), h2d = make_float2(hh1.z, hh1.w);
        float2 r2a = make_float2(rr0.x, rr0.y), r2b = make_float2(rr0.z, rr0.w);
        float2 r2c = make_float2(rr1.x, rr1.y), r2d = make_float2(rr1.z, rr1.w);
#pragma unroll 1
        for (int g = 0; g < 12; ++g) {
            float sh[4], sr[4];
#pragma unroll
            for (int u = 0; u < 4; ++u) {
                int j = wid + 16 * (g * 4 + u);
                const float4* wh = whh4 + (size_t)j * 64;
                const float4* wi = wih4 + (size_t)j * 1088 + 1024;
                float4 a0 = wh[l], a1 = wh[32 + l];
                float4 c0 = wi[l], c1 = wi[32 + l];
                float2 s2 = make_float2(0.f, 0.f), q2 = make_float2(0.f, 0.f);
                fma2(s2, h2a, make_float2(a0.x, a0.y));
                fma2(s2, h2b, make_float2(a0.z, a0.w));
                fma2(s2, h2c, make_float2(a1.x, a1.y));
                fma2(s2, h2d, make_float2(a1.z, a1.w));
                fma2(q2, r2a, make_float2(c0.x, c0.y));
                fma2(q2, r2b, make_float2(c0.z, c0.w));
                fma2(q2, r2c, make_float2(c1.x, c1.y));
                fma2(q2, r2d, make_float2(c1.z, c1.w));
                sh[u] = s2.x + s2.y;
                sr[u] = q2.x + q2.y;
            }
#pragma unroll
            for (int off = 16; off; off >>= 1) {
#pragma unroll
                for (int u = 0; u < 4; ++u) {
                    sh[u] += __shfl_down_sync(0xffffffffu, sh[u], off);
                    sr[u] += __shfl_down_sync(0xffffffffu, sr[u], off);
                }
            }
            if (l == 0) {
#pragma unroll
                for (int u = 0; u < 4; ++u) {
                    int j = wid + 16 * (g * 4 + u);
                    gh_s[j] = sh[u] + b_hh[j];
                    gi_s[j] = sr[u] + g_gif[(size_t)n * 768 + j];
                }
            }
        }
        __syncthreads();

        if (tid < 256) {
            int j = tid;
            float gr = gi_s[j] + gh_s[j];
            float gz = gi_s[256 + j] + gh_s[256 + j];
            float r = 1.f / (1.f + __expf(-gr));
            float z = 1.f / (1.f + __expf(-gz));
            float nn = tanhf(gi_s[512 + j] + r * gh_s[512 + j]);
            float h = (1.f - z) * nn + z * h_s[j];
            h_s[j] = h;
            g_hseq[(size_t)n * 256 + j] = h;
        }
        __syncthreads();

        for (int s = wid; s <= t; s += 16) {
            const float4* kp = k4 + (size_t)s * 64;
            float4 k0 = kp[l], k1 = kp[32 + l];
            float4 hb0 = h4[l], hb1 = h4[32 + l];
            float2 d2 = make_float2(0.f, 0.f);
            fma2(d2, make_float2(k0.x, k0.y), make_float2(hb0.x, hb0.y));
            fma2(d2, make_float2(k0.z, k0.w), make_float2(hb0.z, hb0.w));
            fma2(d2, make_float2(k1.x, k1.y), make_float2(hb1.x, hb1.y));
            fma2(d2, make_float2(k1.z, k1.w), make_float2(hb1.z, hb1.w));
            float d = d2.x + d2.y;
#pragma unroll
            for (int off = 16; off; off >>= 1) d += __shfl_down_sync(0xffffffffu, d, off);
            if (l == 0) sc_s[s] = d;
        }
        __syncthreads();

        if (wid == 0) {
            float v0 = (l <= t) ? sc_s[l] : -1e30f;
            float v1 = (l + 32 <= t) ? sc_s[l + 32] : -1e30f;
            float m = fmaxf(v0, v1);
#pragma unroll
            for (int off = 16; off; off >>= 1) m = fmaxf(m, __shfl_xor_sync(0xffffffffu, m, off));
            float e0 = (l <= t) ? __expf(v0 - m) : 0.f;
            float e1 = (l + 32 <= t) ? __expf(v1 - m) : 0.f;
            float ssum = e0 + e1;
#pragma unroll
            for (int off = 16; off; off >>= 1) ssum += __shfl_xor_sync(0xffffffffu, ssum, off);
            float inv = 1.f / ssum;
            sc_s[l] = e0 * inv;
            sc_s[l + 32] = e1 * inv;
        }
        __syncthreads();

        {
            int k = tid & 255, q = tid >> 8;
            float acc = 0.f;
            for (int s = q; s <= t; s += 2) acc += sc_s[s] * vals_s[s * 256 + k];
            red_s[tid] = acc;
        }
        __syncthreads();
        if (tid < 256) {
            float v = red_s[tid] + red_s[tid + 256];
            r_s[tid] = v;
            g_oseq[(size_t)n * 256 + tid] = v;
        }
        __syncthreads();
    }
}

// ---------------------------------------------------------------------------
// Dueling heads
// ---------------------------------------------------------------------------
__global__ __launch_bounds__(128, 8) void heads_k(const float* __restrict__ adv_w,
                                                  const float* __restrict__ adv_b,
                                                  const float* __restrict__ val_w,
                                                  const float* __restrict__ val_b,
                                                  float* __restrict__ out) {
    const int wid = threadIdx.x >> 5, l = threadIdx.x & 31;
    const int n = blockIdx.x * 4 + wid;
    const float4* gp = (const float4*)(g_gbuf + (size_t)n * 256);
    float4 g0 = gp[l], g1 = gp[l + 32];
    float res[7];
#pragma unroll
    for (int a = 0; a < 7; ++a) {
        const float* wr = (a < 6) ? (adv_w + a * 256) : val_w;
        const float4* wp = (const float4*)wr;
        float4 w0 = wp[l], w1 = wp[l + 32];
        float d = g0.x * w0.x + g0.y * w0.y + g0.z * w0.z + g0.w * w0.w
                + g1.x * w1.x + g1.y * w1.y + g1.z * w1.z + g1.w * w1.w;
#pragma unroll
        for (int off = 16; off; off >>= 1) d += __shfl_down_sync(0xffffffffu, d, off);
        res[a] = d;
    }
    if (l == 0) {
        float adv[6], s = 0.f;
#pragma unroll
        for (int a = 0; a < 6; ++a) { adv[a] = res[a] + adv_b[a]; s += adv[a]; }
        float v = res[6] + val_b[0];
        float mean = s * (1.f / 6.f);
#pragma unroll
        for (int a = 0; a < 6; ++a) out[n * 6 + a] = v + adv[a] - mean;
    }
}

// ---------------------------------------------------------------------------
extern "C" void kernel_launch(void* const* d_in, const int* in_sizes, int n_in,
                              void* d_out, int out_size) {
    const float* obs  = (const float*)d_in[0];
    const float* c1w  = (const float*)d_in[1];
    const float* c1b  = (const float*)d_in[2];
    const float* c2w  = (const float*)d_in[3];
    const float* c2b  = (const float*)d_in[4];
    const float* c3w  = (const float*)d_in[5];
    const float* c3b  = (const float*)d_in[6];
    const float* wkey = (const float*)d_in[7];
    const float* wval = (const float*)d_in[8];
    const float* wih  = (const float*)d_in[9];
    const float* whh  = (const float*)d_in[10];
    const float* bih  = (const float*)d_in[11];
    const float* bhh  = (const float*)d_in[12];
    const float* whid = (const float*)d_in[13];
    const float* advw = (const float*)d_in[14];
    const float* advb = (const float*)d_in[15];
    const float* valw = (const float*)d_in[16];
    const float* valb = (const float*)d_in[17];
    float* out = (float*)d_out;

    (void)in_sizes; (void)n_in; (void)out_size;

    cudaFuncSetAttribute(conv1_k, cudaFuncAttributeMaxDynamicSharedMemorySize, 25872 * 4);
    cudaFuncSetAttribute(conv2_k, cudaFuncAttributeMaxDynamicSharedMemorySize, 49936 * 4);
    cudaFuncSetAttribute(conv3_k, cudaFuncAttributeMaxDynamicSharedMemorySize, 19584 * 4);
    cudaFuncSetAttribute(scan_k,  cudaFuncAttributeMaxDynamicSharedMemorySize, 35392 * 4);

    void *p_feat, *p_keys, *p_vals, *p_gif, *p_hseq, *p_oseq, *p_gbuf;
    cudaGetSymbolAddress(&p_feat, g_feat);
    cudaGetSymbolAddress(&p_keys, g_keys);
    cudaGetSymbolAddress(&p_vals, g_vals);
    cudaGetSymbolAddress(&p_gif,  g_gif);
    cudaGetSymbolAddress(&p_hseq, g_hseq);
    cudaGetSymbolAddress(&p_oseq, g_oseq);
    cudaGetSymbolAddress(&p_gbuf, g_gbuf);

    w2t_k<<<200, 256>>>(c2w);
    w3t_k<<<144, 256>>>(c3w);

    conv1_k<<<2048, 512, 25872 * 4>>>(obs, c1w, c1b);
    conv2_k<<<2048, 512, 49936 * 4>>>(c2b);
    conv3_k<<<1024, 256, 19584 * 4>>>(c3b);

    proj_k<<<dim3(20, 16), 256>>>((const float*)p_feat, wkey, wval, wih, bih,
                                  (float*)p_keys, (float*)p_vals, (float*)p_gif);

    scan_k<<<32, 512, 35392 * 4>>>(wih, whh, bhh);

    gemm_k<<<dim3(4, 32), 256>>>((const float*)p_hseq, whid, (float*)p_gbuf,
                                 2048, 256, 256, 256, nullptr, (const float*)p_oseq, 1);

    heads_k<<<512, 128>>>(advw, advb, valw, valb, out);
}

// round 13
// speedup vs baseline: 1.1624x; 1.0906x over previous
#include <cuda_runtime.h>
#include <cstdint>
#include <cstddef>

// ---------------------------------------------------------------------------
// Packed fp32x2 FMA (sm_103a): 2 independent fp32 MACs per instruction.
// ---------------------------------------------------------------------------
__device__ __forceinline__ void fma2(float2 &c, const float2 a, const float2 b) {
    asm("fma.rn.f32x2 %0, %1, %2, %0;"
        : "+l"(reinterpret_cast<unsigned long long &>(c))
        : "l"(reinterpret_cast<const unsigned long long &>(const_cast<float2 &>(a))),
          "l"(reinterpret_cast<const unsigned long long &>(const_cast<float2 &>(b))));
}

// cp.async helpers (16B)
__device__ __forceinline__ void cpa16(void* s, const void* g) {
    unsigned saddr = (unsigned)__cvta_generic_to_shared(s);
    asm volatile("cp.async.cg.shared.global [%0], [%1], 16;\n" :: "r"(saddr), "l"(g));
}
__device__ __forceinline__ void cpa_commit() { asm volatile("cp.async.commit_group;\n"); }
__device__ __forceinline__ void cpa_wait0()  { asm volatile("cp.async.wait_group 0;\n"); }

// ---------------------------------------------------------------------------
// Scratch (device globals; allocation-free contract)
// ---------------------------------------------------------------------------
__device__ __align__(16) float g_x1[2048u * 32u * 1521u];   // conv1 out
__device__ __align__(16) float g_x2[2048u * 64u * 324u];    // conv2 out
__device__ __align__(16) float g_feat[2048u * 4096u];       // conv3 out / flattened
__device__ __align__(16) float g_keys[2048u * 256u];
__device__ __align__(16) float g_vals[2048u * 256u];
__device__ __align__(16) float g_gif[2048u * 768u];         // feat-part of GRU gi (+b_ih)
__device__ __align__(16) float g_hseq[2048u * 256u];
__device__ __align__(16) float g_oseq[2048u * 256u];
__device__ __align__(16) float g_gbuf[2048u * 256u];        // relu(hseq@Wh^T + oseq)
__device__ __align__(16) float g_w2t[800u * 64u];           // conv2 weights transposed [r][oc]
__device__ __align__(16) float g_w3t[576u * 64u];           // conv3 weights transposed [r][oc]

// ---------------------------------------------------------------------------
// weight transposes (oc-contiguous)
// ---------------------------------------------------------------------------
__global__ void w2t_k(const float* __restrict__ w) {
    int i = blockIdx.x * 256 + threadIdx.x;   // 51200
    if (i < 51200) {
        int r = i >> 6, oc = i & 63;
        g_w2t[i] = w[oc * 800 + r];
    }
}
__global__ void w3t_k(const float* __restrict__ w) {
    int i = blockIdx.x * 256 + threadIdx.x;   // 36864
    if (i < 36864) {
        int r = i >> 6, oc = i & 63;
        g_w3t[i] = w[oc * 576 + r];
    }
}

// ---------------------------------------------------------------------------
// conv1: [2048,3,84,84] -> [2048,32,39,39], 7x7 s2, ReLU. 512 threads.
// Thread tile: 8 oc x 3 consecutive-x outputs; kx register-sliding window
// loaded via 6xLDS.64 + 1 scalar (window base always even here).
// ---------------------------------------------------------------------------
__global__ __launch_bounds__(512, 1) void conv1_k(const float* __restrict__ obs,
                                                  const float* __restrict__ w,
                                                  const float* __restrict__ bia) {
    extern __shared__ float sm[];
    float* in_s = sm;            // 21168
    float* w_s  = sm + 21168;    // 4704
    const int n = blockIdx.x;
    const float* src = obs + (size_t)n * 21168;
    for (int i = threadIdx.x; i < 21168; i += 512) in_s[i] = src[i];
    for (int i = threadIdx.x; i < 4704; i += 512) {
        int oc = i / 147, r = i - oc * 147;
        w_s[r * 32 + oc] = w[i];
    }
    __syncthreads();

    const int tid = threadIdx.x;
    const int oc0 = (tid >> 7) * 8;
    const int pt  = tid & 127;
    float bv[8];
#pragma unroll
    for (int o = 0; o < 8; ++o) bv[o] = bia[oc0 + o];

    for (int it = 0; it < 4; ++it) {
        int seg = pt + 128 * it;
        bool valid = (seg < 507);
        int oy = seg / 13;
        int x0 = 3 * (seg - oy * 13);
        int ibase = valid ? (oy * 168 + 2 * x0) : 0;   // always even

        float2 acc2[3][4];
#pragma unroll
        for (int xi = 0; xi < 3; ++xi)
#pragma unroll
            for (int q = 0; q < 4; ++q) acc2[xi][q] = make_float2(0.f, 0.f);

#pragma unroll 1
        for (int c = 0; c < 3; ++c)
#pragma unroll 1
            for (int ky = 0; ky < 7; ++ky) {
                const float* ip = in_s + c * 7056 + ky * 84 + ibase;
                const float2* ip2 = (const float2*)ip;
                float iv[13];
                float2 t0 = ip2[0], t1 = ip2[1], t2 = ip2[2];
                float2 t3 = ip2[3], t4 = ip2[4], t5 = ip2[5];
                iv[0] = t0.x; iv[1] = t0.y; iv[2] = t1.x; iv[3] = t1.y;
                iv[4] = t2.x; iv[5] = t2.y; iv[6] = t3.x; iv[7] = t3.y;
                iv[8] = t4.x; iv[9] = t4.y; iv[10] = t5.x; iv[11] = t5.y;
                iv[12] = ip[12];
#pragma unroll
                for (int kx = 0; kx < 7; ++kx) {
                    const float4* wp = (const float4*)(w_s + (c * 49 + ky * 7 + kx) * 32 + oc0);
                    float4 wa = wp[0], wb = wp[1];
                    float2 w01 = make_float2(wa.x, wa.y);
                    float2 w23 = make_float2(wa.z, wa.w);
                    float2 w45 = make_float2(wb.x, wb.y);
                    float2 w67 = make_float2(wb.z, wb.w);
#pragma unroll
                    for (int xi = 0; xi < 3; ++xi) {
                        float2 iv2 = make_float2(iv[kx + 2 * xi], iv[kx + 2 * xi]);
                        fma2(acc2[xi][0], iv2, w01);
                        fma2(acc2[xi][1], iv2, w23);
                        fma2(acc2[xi][2], iv2, w45);
                        fma2(acc2[xi][3], iv2, w67);
                    }
                }
            }
        if (valid) {
#pragma unroll
            for (int xi = 0; xi < 3; ++xi) {
                int p = oy * 39 + x0 + xi;
#pragma unroll
                for (int q = 0; q < 4; ++q) {
                    g_x1[((size_t)n * 32 + oc0 + 2 * q + 0) * 1521 + p] =
                        fmaxf(acc2[xi][q].x + bv[2 * q + 0], 0.f);
                    g_x1[((size_t)n * 32 + oc0 + 2 * q + 1) * 1521 + p] =
                        fmaxf(acc2[xi][q].y + bv[2 * q + 1], 0.f);
                }
            }
        }
    }
}

// ---------------------------------------------------------------------------
// conv2: [2048,32,39,39] -> [2048,64,18,18], 5x5 s2, ReLU. 512 threads.
// cp.async double-buffered channel chunks. Thread tile: 8 oc x 6 consecutive-x
// outputs (halves weight-LDS.128 wavefronts per MAC vs 16x3).
// 15-float input window per (c,ky); parity-uniform LDS.64 pattern.
// Rows of 18 = 3 segments of 6; 54 segments (pt < 54 of 64 valid).
// ---------------------------------------------------------------------------
__global__ __launch_bounds__(512, 1) void conv2_k(const float* __restrict__ bia) {
    extern __shared__ float sm[];
    float* in_b[2] = { sm, sm + 12168 };
    float* w_b[2]  = { sm + 24336, sm + 24336 + 12800 };
    const int n = blockIdx.x;
    const int tid = threadIdx.x;
    const int oc0 = (tid >> 6) * 8;      // 8 oc-groups of 8
    const int pt  = tid & 63;
    const bool valid = (pt < 54);
    const int oy = pt / 3;
    const int x0 = 6 * (pt - oy * 3);
    const int ibase = valid ? (oy * 78 + 2 * x0) : 0;   // always even

    {
        const float4* srcI = (const float4*)(g_x1 + (size_t)n * 48672);
        const float4* srcW = (const float4*)(g_w2t);
        float4* dI = (float4*)in_b[0];
        float4* dW = (float4*)w_b[0];
        for (int i = tid; i < 3042; i += 512) cpa16(dI + i, srcI + i);
        for (int i = tid; i < 3200; i += 512) cpa16(dW + i, srcW + i);
        cpa_commit();
    }

    float2 acc2[6][4];
#pragma unroll
    for (int xi = 0; xi < 6; ++xi)
#pragma unroll
        for (int q = 0; q < 4; ++q) acc2[xi][q] = make_float2(0.f, 0.f);

    for (int cc = 0; cc < 4; ++cc) {
        cpa_wait0();
        __syncthreads();
        if (cc < 3) {
            const float4* srcI = (const float4*)(g_x1 + (size_t)n * 48672 + (cc + 1) * 12168);
            const float4* srcW = (const float4*)(g_w2t + (cc + 1) * 12800);
            float4* dI = (float4*)in_b[(cc + 1) & 1];
            float4* dW = (float4*)w_b[(cc + 1) & 1];
            for (int i = tid; i < 3042; i += 512) cpa16(dI + i, srcI + i);
            for (int i = tid; i < 3200; i += 512) cpa16(dW + i, srcW + i);
            cpa_commit();
        }
        const float* in_s = in_b[cc & 1];
        const float* w_s  = w_b[cc & 1];
#pragma unroll 1
        for (int c8 = 0; c8 < 8; ++c8)
#pragma unroll 1
            for (int ky = 0; ky < 5; ++ky) {
                const int woff = c8 * 1521 + ky * 39;      // parity uniform over block
                const float* ip = in_s + woff + ibase;
                float iv[15];
                if ((woff & 1) == 0) {
                    const float2* ip2 = (const float2*)ip;
                    float2 t0 = ip2[0], t1 = ip2[1], t2 = ip2[2], t3 = ip2[3];
                    float2 t4 = ip2[4], t5 = ip2[5], t6 = ip2[6];
                    iv[0] = t0.x; iv[1] = t0.y; iv[2] = t1.x; iv[3] = t1.y;
                    iv[4] = t2.x; iv[5] = t2.y; iv[6] = t3.x; iv[7] = t3.y;
                    iv[8] = t4.x; iv[9] = t4.y; iv[10] = t5.x; iv[11] = t5.y;
                    iv[12] = t6.x; iv[13] = t6.y; iv[14] = ip[14];
                } else {
                    iv[0] = ip[0];
                    const float2* ip2 = (const float2*)(ip + 1);
                    float2 t0 = ip2[0], t1 = ip2[1], t2 = ip2[2], t3 = ip2[3];
                    float2 t4 = ip2[4], t5 = ip2[5], t6 = ip2[6];
                    iv[1] = t0.x; iv[2] = t0.y; iv[3] = t1.x; iv[4] = t1.y;
                    iv[5] = t2.x; iv[6] = t2.y; iv[7] = t3.x; iv[8] = t3.y;
                    iv[9] = t4.x; iv[10] = t4.y; iv[11] = t5.x; iv[12] = t5.y;
                    iv[13] = t6.x; iv[14] = t6.y;
                }
#pragma unroll
                for (int kx = 0; kx < 5; ++kx) {
                    const float4* wp = (const float4*)(w_s + (c8 * 25 + ky * 5 + kx) * 64 + oc0);
                    float4 wa = wp[0], wb = wp[1];
                    float2 wv0 = make_float2(wa.x, wa.y);
                    float2 wv1 = make_float2(wa.z, wa.w);
                    float2 wv2 = make_float2(wb.x, wb.y);
                    float2 wv3 = make_float2(wb.z, wb.w);
#pragma unroll
                    for (int xi = 0; xi < 6; ++xi) {
                        float2 iv2 = make_float2(iv[kx + 2 * xi], iv[kx + 2 * xi]);
                        fma2(acc2[xi][0], iv2, wv0);
                        fma2(acc2[xi][1], iv2, wv1);
                        fma2(acc2[xi][2], iv2, wv2);
                        fma2(acc2[xi][3], iv2, wv3);
                    }
                }
            }
        __syncthreads();
    }
    float bv[8];
#pragma unroll
    for (int o = 0; o < 8; ++o) bv[o] = bia[oc0 + o];
    if (valid) {
#pragma unroll
        for (int xi = 0; xi < 6; ++xi) {
            int p = oy * 18 + x0 + xi;
#pragma unroll
            for (int q = 0; q < 4; ++q) {
                g_x2[((size_t)n * 64 + oc0 + 2 * q + 0) * 324 + p] =
                    fmaxf(acc2[xi][q].x + bv[2 * q + 0], 0.f);
                g_x2[((size_t)n * 64 + oc0 + 2 * q + 1) * 324 + p] =
                    fmaxf(acc2[xi][q].y + bv[2 * q + 1], 0.f);
            }
        }
    }
}

// ---------------------------------------------------------------------------
// conv3: [2048,64,18,18] -> feat [2048,4096], 3x3 s2, ReLU.
// Block = 2 images, 256 threads (128/image). Thread tile = 8 oc x 4 pos.
// K chunked (8 chunks x 8 channels), cp.async double-buffered.
// ---------------------------------------------------------------------------
__global__ __launch_bounds__(256, 2) void conv3_k(const float* __restrict__ bia) {
    extern __shared__ float sm[];
    float* w_b[2]  = { sm, sm + 4608 };
    float* in_b[2] = { sm + 9216, sm + 9216 + 5184 };
    const int tid = threadIdx.x;
    const int img = tid >> 7;
    const int n0 = blockIdx.x * 2;
    const int hid = tid & 127;
    const int oc0 = (hid >> 4) * 8;
    const int posg = hid & 15;

    int ib[4];
#pragma unroll
    for (int j = 0; j < 4; ++j) {
        int p = posg * 4 + j;
        ib[j] = (p >> 3) * 36 + (p & 7) * 2;
    }

    {
        const float4* srcW  = (const float4*)(g_w3t);
        const float4* srcI0 = (const float4*)(g_x2 + (size_t)n0 * 20736);
        const float4* srcI1 = (const float4*)(g_x2 + (size_t)(n0 + 1) * 20736);
        float4* dW = (float4*)w_b[0];
        float4* dI = (float4*)in_b[0];
        for (int i = tid; i < 1152; i += 256) cpa16(dW + i, srcW + i);
        for (int i = tid; i < 648; i += 256) {
            cpa16(dI + i, srcI0 + i);
            cpa16(dI + 648 + i, srcI1 + i);
        }
        cpa_commit();
    }

    float2 acc2[4][4];
#pragma unroll
    for (int j = 0; j < 4; ++j)
#pragma unroll
        for (int q = 0; q < 4; ++q) acc2[j][q] = make_float2(0.f, 0.f);

    for (int cc = 0; cc < 8; ++cc) {
        cpa_wait0();
        __syncthreads();
        if (cc < 7) {
            const float4* srcW  = (const float4*)(g_w3t + (cc + 1) * 4608);
            const float4* srcI0 = (const float4*)(g_x2 + (size_t)n0 * 20736 + (cc + 1) * 2592);
            const float4* srcI1 = (const float4*)(g_x2 + (size_t)(n0 + 1) * 20736 + (cc + 1) * 2592);
            float4* dW = (float4*)w_b[(cc + 1) & 1];
            float4* dI = (float4*)in_b[(cc + 1) & 1];
            for (int i = tid; i < 1152; i += 256) cpa16(dW + i, srcW + i);
            for (int i = tid; i < 648; i += 256) {
                cpa16(dI + i, srcI0 + i);
                cpa16(dI + 648 + i, srcI1 + i);
            }
            cpa_commit();
        }
        const float* w_s  = w_b[cc & 1];
        const float* in_s = in_b[cc & 1] + img * 2592;
#pragma unroll 1
        for (int c8 = 0; c8 < 8; ++c8) {
#pragma unroll
            for (int ky = 0; ky < 3; ++ky)
#pragma unroll
                for (int kx = 0; kx < 3; ++kx) {
                    const float4* wp = (const float4*)(w_s + (c8 * 9 + ky * 3 + kx) * 64 + oc0);
                    float4 wa = wp[0], wb = wp[1];
                    float2 w01 = make_float2(wa.x, wa.y);
                    float2 w23 = make_float2(wa.z, wa.w);
                    float2 w45 = make_float2(wb.x, wb.y);
                    float2 w67 = make_float2(wb.z, wb.w);
                    const float* ip = in_s + c8 * 324 + ky * 18 + kx;
#pragma unroll
                    for (int j = 0; j < 4; ++j) {
                        float iv = ip[ib[j]];
                        float2 iv2 = make_float2(iv, iv);
                        fma2(acc2[j][0], iv2, w01);
                        fma2(acc2[j][1], iv2, w23);
                        fma2(acc2[j][2], iv2, w45);
                        fma2(acc2[j][3], iv2, w67);
                    }
                }
        }
    }

    float* dst = g_feat + (size_t)(n0 + img) * 4096;
    float bv[8];
#pragma unroll
    for (int o = 0; o < 8; ++o) bv[o] = bia[oc0 + o];
#pragma unroll
    for (int j = 0; j < 4; ++j) {
        int p = posg * 4 + j;
#pragma unroll
        for (int q = 0; q < 4; ++q) {
            dst[(oc0 + 2 * q + 0) * 64 + p] = fmaxf(acc2[j][q].x + bv[2 * q + 0], 0.f);
            dst[(oc0 + 2 * q + 1) * 64 + p] = fmaxf(acc2[j][q].y + bv[2 * q + 1], 0.f);
        }
    }
}

// ---------------------------------------------------------------------------
// Fused projection GEMM: 128x64 tiles, 256 threads, 8x4/thread, double-buffered.
// ---------------------------------------------------------------------------
__global__ __launch_bounds__(256, 1) void proj_k(const float* __restrict__ feat,
                                                 const float* __restrict__ wkey,
                                                 const float* __restrict__ wval,
                                                 const float* __restrict__ wih,
                                                 const float* __restrict__ bih,
                                                 float* __restrict__ keys,
                                                 float* __restrict__ vals,
                                                 float* __restrict__ gif) {
    __shared__ float As[2][16][132];
    __shared__ float Bs[2][16][68];
    const int tid = threadIdx.x;
    const int bx = blockIdx.x;
    const int m0 = blockIdx.y * 128;

    const float* Bw; int ldb; float* C; int ldc; int cn0; const float* bias = nullptr;
    if (bx < 4)      { cn0 = bx * 64;        Bw = wkey + (size_t)cn0 * 4096; ldb = 4096; C = keys; ldc = 256; }
    else if (bx < 8) { cn0 = (bx - 4) * 64;  Bw = wval + (size_t)cn0 * 4096; ldb = 4096; C = vals; ldc = 256; }
    else             { cn0 = (bx - 8) * 64;  Bw = wih  + (size_t)cn0 * 4352; ldb = 4352; C = gif;  ldc = 768;
                       bias = bih + cn0; }

    const int lrA = tid >> 1;
    const int lkA = (tid & 1) * 8;
    const int lrB = tid & 63;
    const int lkB = (tid >> 6) * 4;
    const float* aP = feat + (size_t)(m0 + lrA) * 4096 + lkA;
    const float* bP = Bw + (size_t)lrB * ldb + lkB;
    const int tx = tid & 15, ty = tid >> 4;

    float2 acc[8][2];
#pragma unroll
    for (int i = 0; i < 8; ++i) { acc[i][0] = make_float2(0.f, 0.f); acc[i][1] = make_float2(0.f, 0.f); }

    float4 a0 = *(const float4*)(aP);
    float4 a1 = *(const float4*)(aP + 4);
    float4 b0 = *(const float4*)(bP);
    As[0][lkA + 0][lrA] = a0.x; As[0][lkA + 1][lrA] = a0.y;
    As[0][lkA + 2][lrA] = a0.z; As[0][lkA + 3][lrA] = a0.w;
    As[0][lkA + 4][lrA] = a1.x; As[0][lkA + 5][lrA] = a1.y;
    As[0][lkA + 6][lrA] = a1.z; As[0][lkA + 7][lrA] = a1.w;
    Bs[0][lkB + 0][lrB] = b0.x; Bs[0][lkB + 1][lrB] = b0.y;
    Bs[0][lkB + 2][lrB] = b0.z; Bs[0][lkB + 3][lrB] = b0.w;
    __syncthreads();

    int st = 0;
    for (int k0 = 16; k0 < 4096; k0 += 16) {
        a0 = *(const float4*)(aP + k0);
        a1 = *(const float4*)(aP + k0 + 4);
        b0 = *(const float4*)(bP + k0);
#pragma unroll
        for (int kk = 0; kk < 16; ++kk) {
            float4 af0 = *(const float4*)(&As[st][kk][ty * 8]);
            float4 af1 = *(const float4*)(&As[st][kk][ty * 8 + 4]);
            float4 bf  = *(const float4*)(&Bs[st][kk][tx * 4]);
            float av[8] = {af0.x, af0.y, af0.z, af0.w, af1.x, af1.y, af1.z, af1.w};
            float2 bb0 = make_float2(bf.x, bf.y), bb1 = make_float2(bf.z, bf.w);
#pragma unroll
            for (int i = 0; i < 8; ++i) {
                float2 a2 = make_float2(av[i], av[i]);
                fma2(acc[i][0], a2, bb0);
                fma2(acc[i][1], a2, bb1);
            }
        }
        int ns = st ^ 1;
        As[ns][lkA + 0][lrA] = a0.x; As[ns][lkA + 1][lrA] = a0.y;
        As[ns][lkA + 2][lrA] = a0.z; As[ns][lkA + 3][lrA] = a0.w;
        As[ns][lkA + 4][lrA] = a1.x; As[ns][lkA + 5][lrA] = a1.y;
        As[ns][lkA + 6][lrA] = a1.z; As[ns][lkA + 7][lrA] = a1.w;
        Bs[ns][lkB + 0][lrB] = b0.x; Bs[ns][lkB + 1][lrB] = b0.y;
        Bs[ns][lkB + 2][lrB] = b0.z; Bs[ns][lkB + 3][lrB] = b0.w;
        __syncthreads();
        st = ns;
    }
#pragma unroll
    for (int kk = 0; kk < 16; ++kk) {
        float4 af0 = *(const float4*)(&As[st][kk][ty * 8]);
        float4 af1 = *(const float4*)(&As[st][kk][ty * 8 + 4]);
        float4 bf  = *(const float4*)(&Bs[st][kk][tx * 4]);
        float av[8] = {af0.x, af0.y, af0.z, af0.w, af1.x, af1.y, af1.z, af1.w};
        float2 bb0 = make_float2(bf.x, bf.y), bb1 = make_float2(bf.z, bf.w);
#pragma unroll
        for (int i = 0; i < 8; ++i) {
            float2 a2 = make_float2(av[i], av[i]);
            fma2(acc[i][0], a2, bb0);
            fma2(acc[i][1], a2, bb1);
        }
    }

    float bload[4] = {0.f, 0.f, 0.f, 0.f};
    if (bias) {
#pragma unroll
        for (int q = 0; q < 4; ++q) bload[q] = bias[tx * 4 + q];
    }
#pragma unroll
    for (int i = 0; i < 8; ++i) {
        int m = m0 + ty * 8 + i;
        float4 v;
        v.x = acc[i][0].x + bload[0]; v.y = acc[i][0].y + bload[1];
        v.z = acc[i][1].x + bload[2]; v.w = acc[i][1].y + bload[3];
        *(float4*)(C + (size_t)m * ldc + cn0 + tx * 4) = v;
    }
}

// ---------------------------------------------------------------------------
// Generic GEMM (whid GEMM): C = A*B^T (+bias)(+addm)(relu)
// ---------------------------------------------------------------------------
__global__ __launch_bounds__(256, 1) void gemm_k(const float* __restrict__ A,
                                                 const float* __restrict__ B,
                                                 float* __restrict__ C,
                                                 int M, int N, int K, int ldb,
                                                 const float* __restrict__ bias,
                                                 const float* __restrict__ addm,
                                                 int relu) {
    __shared__ float As[16][64];
    __shared__ float Bs[16][64];
    const int tid = threadIdx.x;
    const int m0 = blockIdx.y * 64, n0 = blockIdx.x * 64;
    const int lr = tid >> 2;
    const int lc = (tid & 3) * 4;
    const int tx = tid & 15, ty = tid >> 4;

    float2 acc2[4][2];
#pragma unroll
    for (int i = 0; i < 4; ++i) { acc2[i][0] = make_float2(0.f, 0.f); acc2[i][1] = make_float2(0.f, 0.f); }

    for (int k0 = 0; k0 < K; k0 += 16) {
        __syncthreads();
        float4 va = *(const float4*)(A + (size_t)(m0 + lr) * K + k0 + lc);
        float4 vb = *(const float4*)(B + (size_t)(n0 + lr) * ldb + k0 + lc);
        As[lc + 0][lr] = va.x; As[lc + 1][lr] = va.y;
        As[lc + 2][lr] = va.z; As[lc + 3][lr] = va.w;
        Bs[lc + 0][lr] = vb.x; Bs[lc + 1][lr] = vb.y;
        Bs[lc + 2][lr] = vb.z; Bs[lc + 3][lr] = vb.w;
        __syncthreads();
#pragma unroll
        for (int kk = 0; kk < 16; ++kk) {
            float4 a = *(const float4*)(&As[kk][ty * 4]);
            float4 b = *(const float4*)(&Bs[kk][tx * 4]);
            float2 b0 = make_float2(b.x, b.y), b1 = make_float2(b.z, b.w);
            float av[4] = {a.x, a.y, a.z, a.w};
#pragma unroll
            for (int i = 0; i < 4; ++i) {
                float2 a2 = make_float2(av[i], av[i]);
                fma2(acc2[i][0], a2, b0);
                fma2(acc2[i][1], a2, b1);
            }
        }
    }

#pragma unroll
    for (int i = 0; i < 4; ++i) {
        int m = m0 + ty * 4 + i;
        int nn = n0 + tx * 4;
        float4 v;
        v.x = acc2[i][0].x; v.y = acc2[i][0].y;
        v.z = acc2[i][1].x; v.w = acc2[i][1].y;
        if (bias) {
            v.x += bias[nn + 0]; v.y += bias[nn + 1];
            v.z += bias[nn + 2]; v.w += bias[nn + 3];
        }
        if (addm) {
            float4 ad = *(const float4*)(addm + (size_t)m * N + nn);
            v.x += ad.x; v.y += ad.y; v.z += ad.z; v.w += ad.w;
        }
        if (relu) {
            v.x = fmaxf(v.x, 0.f); v.y = fmaxf(v.y, 0.f);
            v.z = fmaxf(v.z, 0.f); v.w = fmaxf(v.w, 0.f);
        }
        *(float4*)(C + (size_t)m * N + nn) = v;
    }
}

// ---------------------------------------------------------------------------
// Sequential GRU + causal episodic attention scan (32 blocks, 512 threads).
// ---------------------------------------------------------------------------
__global__ __launch_bounds__(512, 1) void scan_k(const float* __restrict__ w_ih,
                                                 const float* __restrict__ w_hh,
                                                 const float* __restrict__ b_hh) {
    extern __shared__ float sm[];
    float* keys_s = sm;             // 16384
    float* vals_s = sm + 16384;     // 16384
    float* h_s    = sm + 32768;     // 256
    float* r_s    = sm + 33024;     // 256
    float* gi_s   = sm + 33280;     // 768
    float* gh_s   = sm + 34048;     // 768
    float* sc_s   = sm + 34816;     // 64
    float* red_s  = sm + 34880;     // 512

    const int b = blockIdx.x;
    const int tid = threadIdx.x;
    const int wid = tid >> 5, l = tid & 31;

    for (int i = tid; i < 16384; i += 512) {
        keys_s[i] = g_keys[(size_t)b * 16384 + i];
        vals_s[i] = g_vals[(size_t)b * 16384 + i];
    }
    if (tid < 256) { h_s[tid] = 0.f; r_s[tid] = 0.f; }
    __syncthreads();

    const float4* whh4 = (const float4*)w_hh;
    const float4* wih4 = (const float4*)w_ih;
    const float4* h4 = (const float4*)h_s;
    const float4* r4 = (const float4*)r_s;
    const float4* k4 = (const float4*)keys_s;

    for (int t = 0; t < 64; ++t) {
        const int n = b * 64 + t;

        float4 hh0 = h4[l], hh1 = h4[32 + l];
        float4 rr0 = r4[l], rr1 = r4[32 + l];
        float2 h2a = make_float2(hh0.x, hh0.y), h2b = make_float2(hh0.z, hh0.w);
        float2 h2c = make_float2(hh1.x, hh1.y), h2d = make_float2(hh1.z, hh1.w);
        float2 r2a = make_float2(rr0.x, rr0.y), r2b = make_float2(rr0.z, rr0.w);
        float2 r2c = make_float2(rr1.x, rr1.y), r2d = make_float2(rr1.z, rr1.w);
#pragma unroll 1
        for (int g = 0; g < 12; ++g) {
            float sh[4], sr[4];
#pragma unroll
            for (int u = 0; u < 4; ++u) {
                int j = wid + 16 * (g * 4 + u);
                const float4* wh = whh4 + (size_t)j * 64;
                const float4* wi = wih4 + (size_t)j * 1088 + 1024;
                float4 a0 = wh[l], a1 = wh[32 + l];
                float4 c0 = wi[l], c1 = wi[32 + l];
                float2 s2 = make_float2(0.f, 0.f), q2 = make_float2(0.f, 0.f);
                fma2(s2, h2a, make_float2(a0.x, a0.y));
                fma2(s2, h2b, make_float2(a0.z, a0.w));
                fma2(s2, h2c, make_float2(a1.x, a1.y));
                fma2(s2, h2d, make_float2(a1.z, a1.w));
                fma2(q2, r2a, make_float2(c0.x, c0.y));
                fma2(q2, r2b, make_float2(c0.z, c0.w));
                fma2(q2, r2c, make_float2(c1.x, c1.y));
                fma2(q2, r2d, make_float2(c1.z, c1.w));
                sh[u] = s2.x + s2.y;
                sr[u] = q2.x + q2.y;
            }
#pragma unroll
            for (int off = 16; off; off >>= 1) {
#pragma unroll
                for (int u = 0; u < 4; ++u) {
                    sh[u] += __shfl_down_sync(0xffffffffu, sh[u], off);
                    sr[u] += __shfl_down_sync(0xffffffffu, sr[u], off);
                }
            }
            if (l == 0) {
#pragma unroll
                for (int u = 0; u < 4; ++u) {
                    int j = wid + 16 * (g * 4 + u);
                    gh_s[j] = sh[u] + b_hh[j];
                    gi_s[j] = sr[u] + g_gif[(size_t)n * 768 + j];
                }
            }
        }
        __syncthreads();

        if (tid < 256) {
            int j = tid;
            float gr = gi_s[j] + gh_s[j];
            float gz = gi_s[256 + j] + gh_s[256 + j];
            float r = 1.f / (1.f + __expf(-gr));
            float z = 1.f / (1.f + __expf(-gz));
            float nn = tanhf(gi_s[512 + j] + r * gh_s[512 + j]);
            float h = (1.f - z) * nn + z * h_s[j];
            h_s[j] = h;
            g_hseq[(size_t)n * 256 + j] = h;
        }
        __syncthreads();

        for (int s = wid; s <= t; s += 16) {
            const float4* kp = k4 + (size_t)s * 64;
            float4 k0 = kp[l], k1 = kp[32 + l];
            float4 hb0 = h4[l], hb1 = h4[32 + l];
            float2 d2 = make_float2(0.f, 0.f);
            fma2(d2, make_float2(k0.x, k0.y), make_float2(hb0.x, hb0.y));
            fma2(d2, make_float2(k0.z, k0.w), make_float2(hb0.z, hb0.w));
            fma2(d2, make_float2(k1.x, k1.y), make_float2(hb1.x, hb1.y));
            fma2(d2, make_float2(k1.z, k1.w), make_float2(hb1.z, hb1.w));
            float d = d2.x + d2.y;
#pragma unroll
            for (int off = 16; off; off >>= 1) d += __shfl_down_sync(0xffffffffu, d, off);
            if (l == 0) sc_s[s] = d;
        }
        __syncthreads();

        if (wid == 0) {
            float v0 = (l <= t) ? sc_s[l] : -1e30f;
            float v1 = (l + 32 <= t) ? sc_s[l + 32] : -1e30f;
            float m = fmaxf(v0, v1);
#pragma unroll
            for (int off = 16; off; off >>= 1) m = fmaxf(m, __shfl_xor_sync(0xffffffffu, m, off));
            float e0 = (l <= t) ? __expf(v0 - m) : 0.f;
            float e1 = (l + 32 <= t) ? __expf(v1 - m) : 0.f;
            float ssum = e0 + e1;
#pragma unroll
            for (int off = 16; off; off >>= 1) ssum += __shfl_xor_sync(0xffffffffu, ssum, off);
            float inv = 1.f / ssum;
            sc_s[l] = e0 * inv;
            sc_s[l + 32] = e1 * inv;
        }
        __syncthreads();

        {
            int k = tid & 255, q = tid >> 8;
            float acc = 0.f;
            for (int s = q; s <= t; s += 2) acc += sc_s[s] * vals_s[s * 256 + k];
            red_s[tid] = acc;
        }
        __syncthreads();
        if (tid < 256) {
            float v = red_s[tid] + red_s[tid + 256];
            r_s[tid] = v;
            g_oseq[(size_t)n * 256 + tid] = v;
        }
        __syncthreads();
    }
}

// ---------------------------------------------------------------------------
// Dueling heads
// ---------------------------------------------------------------------------
__global__ __launch_bounds__(128, 8) void heads_k(const float* __restrict__ adv_w,
                                                  const float* __restrict__ adv_b,
                                                  const float* __restrict__ val_w,
                                                  const float* __restrict__ val_b,
                                                  float* __restrict__ out) {
    const int wid = threadIdx.x >> 5, l = threadIdx.x & 31;
    const int n = blockIdx.x * 4 + wid;
    const float4* gp = (const float4*)(g_gbuf + (size_t)n * 256);
    float4 g0 = gp[l], g1 = gp[l + 32];
    float res[7];
#pragma unroll
    for (int a = 0; a < 7; ++a) {
        const float* wr = (a < 6) ? (adv_w + a * 256) : val_w;
        const float4* wp = (const float4*)wr;
        float4 w0 = wp[l], w1 = wp[l + 32];
        float d = g0.x * w0.x + g0.y * w0.y + g0.z * w0.z + g0.w * w0.w
                + g1.x * w1.x + g1.y * w1.y + g1.z * w1.z + g1.w * w1.w;
#pragma unroll
        for (int off = 16; off; off >>= 1) d += __shfl_down_sync(0xffffffffu, d, off);
        res[a] = d;
    }
    if (l == 0) {
        float adv[6], s = 0.f;
#pragma unroll
        for (int a = 0; a < 6; ++a) { adv[a] = res[a] + adv_b[a]; s += adv[a]; }
        float v = res[6] + val_b[0];
        float mean = s * (1.f / 6.f);
#pragma unroll
        for (int a = 0; a < 6; ++a) out[n * 6 + a] = v + adv[a] - mean;
    }
}

// ---------------------------------------------------------------------------
extern "C" void kernel_launch(void* const* d_in, const int* in_sizes, int n_in,
                              void* d_out, int out_size) {
    const float* obs  = (const float*)d_in[0];
    const float* c1w  = (const float*)d_in[1];
    const float* c1b  = (const float*)d_in[2];
    const float* c2w  = (const float*)d_in[3];
    const float* c2b  = (const float*)d_in[4];
    const float* c3w  = (const float*)d_in[5];
    const float* c3b  = (const float*)d_in[6];
    const float* wkey = (const float*)d_in[7];
    const float* wval = (const float*)d_in[8];
    const float* wih  = (const float*)d_in[9];
    const float* whh  = (const float*)d_in[10];
    const float* bih  = (const float*)d_in[11];
    const float* bhh  = (const float*)d_in[12];
    const float* whid = (const float*)d_in[13];
    const float* advw = (const float*)d_in[14];
    const float* advb = (const float*)d_in[15];
    const float* valw = (const float*)d_in[16];
    const float* valb = (const float*)d_in[17];
    float* out = (float*)d_out;

    (void)in_sizes; (void)n_in; (void)out_size;

    cudaFuncSetAttribute(conv1_k, cudaFuncAttributeMaxDynamicSharedMemorySize, 25872 * 4);
    cudaFuncSetAttribute(conv2_k, cudaFuncAttributeMaxDynamicSharedMemorySize, 49936 * 4);
    cudaFuncSetAttribute(conv3_k, cudaFuncAttributeMaxDynamicSharedMemorySize, 19584 * 4);
    cudaFuncSetAttribute(scan_k,  cudaFuncAttributeMaxDynamicSharedMemorySize, 35392 * 4);

    void *p_feat, *p_keys, *p_vals, *p_gif, *p_hseq, *p_oseq, *p_gbuf;
    cudaGetSymbolAddress(&p_feat, g_feat);
    cudaGetSymbolAddress(&p_keys, g_keys);
    cudaGetSymbolAddress(&p_vals, g_vals);
    cudaGetSymbolAddress(&p_gif,  g_gif);
    cudaGetSymbolAddress(&p_hseq, g_hseq);
    cudaGetSymbolAddress(&p_oseq, g_oseq);
    cudaGetSymbolAddress(&p_gbuf, g_gbuf);

    w2t_k<<<200, 256>>>(c2w);
    w3t_k<<<144, 256>>>(c3w);

    conv1_k<<<2048, 512, 25872 * 4>>>(obs, c1w, c1b);
    conv2_k<<<2048, 512, 49936 * 4>>>(c2b);
    conv3_k<<<1024, 256, 19584 * 4>>>(c3b);

    proj_k<<<dim3(20, 16), 256>>>((const float*)p_feat, wkey, wval, wih, bih,
                                  (float*)p_keys, (float*)p_vals, (float*)p_gif);

    scan_k<<<32, 512, 35392 * 4>>>(wih, whh, bhh);

    gemm_k<<<dim3(4, 32), 256>>>((const float*)p_hseq, whid, (float*)p_gbuf,
                                 2048, 256, 256, 256, nullptr, (const float*)p_oseq, 1);

    heads_k<<<512, 128>>>(advw, advb, valw, valb, out);
}